// round 11
// baseline (speedup 1.0000x reference)
#include <cuda_runtime.h>
#include <cstdint>

#define NSUB  64
#define NPTS  65536
#define TPB   128         // 4 warps; warp owns 32 of the tile's 128 points
#define TILES 8           // 128-pt tiles per CTA
#define GRIDX 18          // slots per subdomain = 18432 (max expected ~16900)
#define STR   68          // H row stride (floats): conflict-free frag access
#define RWIN  0.1171875f  // 7.5/64 — PoU window radius (tail < ~5e-5 rel)

// Static device scratch (no allocation).
__device__ float    g_u[NSUB * NPTS];
// Fragment-packed tf32 weights: [l][s][ ((kk*4+c)*32 + lane)*4 + i ]
__device__ uint32_t gBp[2][NSUB][4096];
__device__ int      g_bin_cnt[64];
__device__ int      g_bin_idx[64][NPTS];

// ---------------------------------------------------------------------------
// Scalar helpers
// ---------------------------------------------------------------------------
__device__ __forceinline__ float tanh_hw(float x) {
    float r; asm("tanh.approx.f32 %0, %1;" : "=f"(r) : "f"(x)); return r;
}
__device__ __forceinline__ float tanh_acc(float x) {
    float e; asm("ex2.approx.f32 %0, %1;" : "=f"(e) : "f"(x * 2.8853900817779268f));
    float r; asm("rcp.approx.f32 %0, %1;" : "=f"(r) : "f"(e + 1.0f));
    return fmaf(-2.0f, r, 1.0f);
}
__device__ __forceinline__ uint32_t f2tf32(float f) {
    uint32_t r; asm("cvt.rna.tf32.f32 %0, %1;" : "=r"(r) : "f"(f)); return r;
}

// PoU bin window — single definition shared by MLP (writer) and reduce (reader).
__device__ __forceinline__ void window_of(int s, int& lo, int& hi) {
    const float c = (float)s * (1.0f / 63.0f);
    int l = (int)floorf((c - RWIN) * 64.0f);
    int h = (int)floorf((c + RWIN) * 64.0f);
    lo = l < 0 ? 0 : l;
    hi = h > 63 ? 63 : h;
}
__device__ __forceinline__ int bin_of(float x) {
    int b = (int)(x * 64.0f);
    return b < 0 ? 0 : (b > 63 ? 63 : b);
}

// mma.sync m16n8k8 tf32 (baseline PTX, tensor pipe). A operands carry raw f32
// bits: tf32 HMMA reads only the top 19 bits (truncation, err ~2^-11).
__device__ __forceinline__ void mma8(float& d0, float& d1, float& d2, float& d3,
                                     uint32_t a0, uint32_t a1, uint32_t a2, uint32_t a3,
                                     uint32_t b0, uint32_t b1) {
    asm volatile(
        "mma.sync.aligned.m16n8k8.row.col.f32.tf32.tf32.f32 "
        "{%0,%1,%2,%3}, {%4,%5,%6,%7}, {%8,%9}, {%0,%1,%2,%3};"
        : "+f"(d0), "+f"(d1), "+f"(d2), "+f"(d3)
        : "r"(a0), "r"(a1), "r"(a2), "r"(a3), "r"(b0), "r"(b1));
}

// ---------------------------------------------------------------------------
// Prep: fragment-packed layout (unchanged from R10).
// ---------------------------------------------------------------------------
__global__ void prep_weights(const float* __restrict__ W1,
                             const float* __restrict__ W2) {
    const int i = blockIdx.x * 256 + threadIdx.x;         // over 2*64*4096
    if (i >= 2 * NSUB * 4096) return;
    const int l  = i >> 18;
    const int r  = i & 262143;
    const int s  = r >> 12;
    const int q  = r & 4095;
    const int kk = q >> 9;
    const int c  = (q >> 7) & 3;
    const int lane = (q >> 2) & 31;
    const int ii = q & 3;
    const int j  = c * 4 + ii;         // 0..15
    const int nt = j & 7, wh = j >> 3;
    const int g  = lane >> 2, t = lane & 3;
    const int k  = kk * 8 + t + wh * 4;
    const int n  = nt * 8 + g;
    const float* W = l ? W2 : W1;
    gBp[l][s][q] = f2tf32(W[s * 4096 + n * 64 + k]);
}
__global__ void zero_counters() { g_bin_cnt[threadIdx.x] = 0; }
__global__ void bin_points(const float* __restrict__ X) {
    const int n = blockIdx.x * 256 + threadIdx.x;
    const int b = bin_of(X[n]);
    const int p = atomicAdd(&g_bin_cnt[b], 1);
    g_bin_idx[b][p] = n;
}

// ---------------------------------------------------------------------------
// Shared memory (~36 KB -> 4 CTAs/SM; regs capped at 128 by launch_bounds,
// RF: 128*128*4 = 65536 exactly). B fragments stay in global: lane-uniform,
// warp-identical LDG.128 -> L1-resident (83 KB L1 left after 4x36KB smem).
// ---------------------------------------------------------------------------
struct __align__(16) SMem {
    uint32_t H[4][32 * STR];       // per-warp activations
    float w0[64], b0[64], b1[64], b2[64], w3[64];
    float b3;
    int cum[24];
};

__device__ __forceinline__ int slot_to_n(const int* __restrict__ cum, int nb,
                                         int lo, int slot) {
    int j = 0;
#pragma unroll 1
    while (j + 1 < nb && slot >= cum[j + 1]) j++;
    return g_bin_idx[lo + j][slot - cum[j]];
}

// ---------------------------------------------------------------------------
// Main kernel. Fragment maps (m16n8k8, g = lane>>2, t = lane&3):
//   A: a0=(g,t) a1=(g+8,t) a2=(g,t+4) a3=(g+8,t+4)
//   B (packed): u0..u3 per kk -> bv0[nt], bv1[nt]
//   D: c0=(g,2t) c1=(g,2t+1) c2=(g+8,2t) c3=(g+8,2t+1)
// ---------------------------------------------------------------------------
__global__ __launch_bounds__(TPB, 4)
void fbpinn_mlp(const float* __restrict__ X,
                const float* __restrict__ W0g, const float* __restrict__ B0g,
                const float* __restrict__ B1g, const float* __restrict__ B2g,
                const float* __restrict__ W3g, const float* __restrict__ B3g) {
    extern __shared__ char smraw[];
    SMem* sm = (SMem*)smraw;

    const int s    = blockIdx.y;
    const int tid  = threadIdx.x;
    const int wid  = tid >> 5;
    const int lane = tid & 31;
    const int g    = lane >> 2;
    const int t    = lane & 3;
    const int wb   = wid * 32;

    int lo, hi;
    window_of(s, lo, hi);
    const int nb = hi - lo + 1;

    if (tid < nb) sm->cum[tid + 1] = g_bin_cnt[lo + tid];
    if (tid == 0) sm->cum[0] = 0;
    __syncthreads();
    if (tid == 0) {
        int a = 0;
#pragma unroll 1
        for (int j = 1; j <= nb; j++) { a += sm->cum[j]; sm->cum[j] = a; }
    }
    __syncthreads();
    const int total = sm->cum[nb];
    if (blockIdx.x * (TILES * TPB) >= total) return;

    // cooperative smem fill (params only — B stays in global/L1)
    {
        if (tid < 64) {
            sm->w0[tid] = W0g[s * 64 + tid];
            sm->b0[tid] = B0g[s * 64 + tid];
            sm->b1[tid] = B1g[s * 64 + tid];
            sm->b2[tid] = B2g[s * 64 + tid];
            sm->w3[tid] = W3g[s * 64 + tid];
        }
        if (tid == 64) sm->b3 = B3g[s];
    }
    __syncthreads();

    const float b3v = sm->b3;
    uint32_t* Hu = sm->H[wid];
    const uint4* bp1 = (const uint4*)&gBp[0][s][0];
    const uint4* bp2 = (const uint4*)&gBp[1][s][0];
    float acc[8][2][4];

#pragma unroll 1
    for (int tile = 0; tile < TILES; tile++) {
        const int tb = (blockIdx.x * TILES + tile) * TPB;
        if (tb >= total) break;

        const int r0 = tb + wb + g, r1 = r0 + 8, r2 = r0 + 16, r3 = r0 + 24;
        int n0 = -1, n1 = -1, n2 = -1, n3 = -1;
        float x0 = 0.f, x1 = 0.f, x2 = 0.f, x3 = 0.f;
        if (r0 < total) { n0 = slot_to_n(sm->cum, nb, lo, r0); x0 = X[n0]; }
        if (r1 < total) { n1 = slot_to_n(sm->cum, nb, lo, r1); x1 = X[n1]; }
        if (r2 < total) { n2 = slot_to_n(sm->cum, nb, lo, r2); x2 = X[n2]; }
        if (r3 < total) { n3 = slot_to_n(sm->cum, nb, lo, r3); x3 = X[n3]; }

        // ================= Layer 1 (A built on the fly from layer 0) ========
#pragma unroll
        for (int nt = 0; nt < 8; nt++) {
            const float2 bb = *(const float2*)&sm->b1[nt * 8 + 2 * t];
#pragma unroll
            for (int mt = 0; mt < 2; mt++) {
                acc[nt][mt][0] = bb.x; acc[nt][mt][1] = bb.y;
                acc[nt][mt][2] = bb.x; acc[nt][mt][3] = bb.y;
            }
        }
#pragma unroll
        for (int kk = 0; kk < 8; kk++) {
            const int k0 = kk * 8;
            const float wc0 = sm->w0[k0 + t],     bc0 = sm->b0[k0 + t];
            const float wc1 = sm->w0[k0 + t + 4], bc1 = sm->b0[k0 + t + 4];
            uint32_t a0[4], a1[4];
            a0[0] = __float_as_uint(tanh_hw(fmaf(wc0, x0, bc0)));
            a0[1] = __float_as_uint(tanh_hw(fmaf(wc0, x1, bc0)));
            a0[2] = __float_as_uint(tanh_hw(fmaf(wc1, x0, bc1)));
            a0[3] = __float_as_uint(tanh_hw(fmaf(wc1, x1, bc1)));
            a1[0] = __float_as_uint(tanh_hw(fmaf(wc0, x2, bc0)));
            a1[1] = __float_as_uint(tanh_hw(fmaf(wc0, x3, bc0)));
            a1[2] = __float_as_uint(tanh_hw(fmaf(wc1, x2, bc1)));
            a1[3] = __float_as_uint(tanh_hw(fmaf(wc1, x3, bc1)));
            // packed B fragments: 4 x LDG.128, warp-identical -> L1-resident
            const uint4 u0 = __ldg(&bp1[(kk * 4 + 0) * 32 + lane]);
            const uint4 u1 = __ldg(&bp1[(kk * 4 + 1) * 32 + lane]);
            const uint4 u2 = __ldg(&bp1[(kk * 4 + 2) * 32 + lane]);
            const uint4 u3 = __ldg(&bp1[(kk * 4 + 3) * 32 + lane]);
            const uint32_t bv0[8] = {u0.x, u0.y, u0.z, u0.w, u1.x, u1.y, u1.z, u1.w};
            const uint32_t bv1[8] = {u2.x, u2.y, u2.z, u2.w, u3.x, u3.y, u3.z, u3.w};
#pragma unroll
            for (int nt = 0; nt < 8; nt++) {
                mma8(acc[nt][0][0], acc[nt][0][1], acc[nt][0][2], acc[nt][0][3],
                     a0[0], a0[1], a0[2], a0[3], bv0[nt], bv1[nt]);
                mma8(acc[nt][1][0], acc[nt][1][1], acc[nt][1][2], acc[nt][1][3],
                     a1[0], a1[1], a1[2], a1[3], bv0[nt], bv1[nt]);
            }
        }

        // epilogue 1: tanh -> raw f32 bits -> per-warp H
        __syncwarp();
#pragma unroll
        for (int nt = 0; nt < 8; nt++) {
#pragma unroll
            for (int mt = 0; mt < 2; mt++) {
                uint2 lov, hiv;
                lov.x = __float_as_uint(tanh_hw(acc[nt][mt][0]));
                lov.y = __float_as_uint(tanh_hw(acc[nt][mt][1]));
                hiv.x = __float_as_uint(tanh_hw(acc[nt][mt][2]));
                hiv.y = __float_as_uint(tanh_hw(acc[nt][mt][3]));
                *(uint2*)&Hu[(mt * 16 + g) * STR + nt * 8 + 2 * t]     = lov;
                *(uint2*)&Hu[(mt * 16 + g + 8) * STR + nt * 8 + 2 * t] = hiv;
            }
        }
        __syncwarp();

        // ================= Layer 2 (A from H) ===============================
#pragma unroll
        for (int nt = 0; nt < 8; nt++) {
            const float2 bb = *(const float2*)&sm->b2[nt * 8 + 2 * t];
#pragma unroll
            for (int mt = 0; mt < 2; mt++) {
                acc[nt][mt][0] = bb.x; acc[nt][mt][1] = bb.y;
                acc[nt][mt][2] = bb.x; acc[nt][mt][3] = bb.y;
            }
        }
#pragma unroll
        for (int kk = 0; kk < 8; kk++) {
            const int k0 = kk * 8;
            uint32_t a0[4], a1[4];
            a0[0] = Hu[(g) * STR + k0 + t];
            a0[1] = Hu[(g + 8) * STR + k0 + t];
            a0[2] = Hu[(g) * STR + k0 + t + 4];
            a0[3] = Hu[(g + 8) * STR + k0 + t + 4];
            a1[0] = Hu[(g + 16) * STR + k0 + t];
            a1[1] = Hu[(g + 24) * STR + k0 + t];
            a1[2] = Hu[(g + 16) * STR + k0 + t + 4];
            a1[3] = Hu[(g + 24) * STR + k0 + t + 4];
            const uint4 u0 = __ldg(&bp2[(kk * 4 + 0) * 32 + lane]);
            const uint4 u1 = __ldg(&bp2[(kk * 4 + 1) * 32 + lane]);
            const uint4 u2 = __ldg(&bp2[(kk * 4 + 2) * 32 + lane]);
            const uint4 u3 = __ldg(&bp2[(kk * 4 + 3) * 32 + lane]);
            const uint32_t bv0[8] = {u0.x, u0.y, u0.z, u0.w, u1.x, u1.y, u1.z, u1.w};
            const uint32_t bv1[8] = {u2.x, u2.y, u2.z, u2.w, u3.x, u3.y, u3.z, u3.w};
#pragma unroll
            for (int nt = 0; nt < 8; nt++) {
                mma8(acc[nt][0][0], acc[nt][0][1], acc[nt][0][2], acc[nt][0][3],
                     a0[0], a0[1], a0[2], a0[3], bv0[nt], bv1[nt]);
                mma8(acc[nt][1][0], acc[nt][1][1], acc[nt][1][2], acc[nt][1][3],
                     a1[0], a1[1], a1[2], a1[3], bv0[nt], bv1[nt]);
            }
        }

        // ===== output layer (fp32): u[row] = b3 + sum_n w3[n]*tanh(acc) =====
        {
            float u0 = 0.f, u1 = 0.f, u2 = 0.f, u3 = 0.f;
#pragma unroll
            for (int nt = 0; nt < 8; nt++) {
                const float2 w3p = *(const float2*)&sm->w3[nt * 8 + 2 * t];
                u0 = fmaf(w3p.x, tanh_hw(acc[nt][0][0]), u0);
                u0 = fmaf(w3p.y, tanh_hw(acc[nt][0][1]), u0);
                u1 = fmaf(w3p.x, tanh_hw(acc[nt][0][2]), u1);
                u1 = fmaf(w3p.y, tanh_hw(acc[nt][0][3]), u1);
                u2 = fmaf(w3p.x, tanh_hw(acc[nt][1][0]), u2);
                u2 = fmaf(w3p.y, tanh_hw(acc[nt][1][1]), u2);
                u3 = fmaf(w3p.x, tanh_hw(acc[nt][1][2]), u3);
                u3 = fmaf(w3p.y, tanh_hw(acc[nt][1][3]), u3);
            }
#pragma unroll
            for (int d = 1; d < 4; d <<= 1) {
                u0 += __shfl_xor_sync(0xffffffffu, u0, d);
                u1 += __shfl_xor_sync(0xffffffffu, u1, d);
                u2 += __shfl_xor_sync(0xffffffffu, u2, d);
                u3 += __shfl_xor_sync(0xffffffffu, u3, d);
            }
            if (t == 0) {
                float* up = g_u + s * NPTS;
                if (n0 >= 0) up[n0] = u0 + b3v;
                if (n1 >= 0) up[n1] = u1 + b3v;
                if (n2 >= 0) up[n2] = u2 + b3v;
                if (n3 >= 0) up[n3] = u3 + b3v;
            }
        }
    }
}

// ---------------------------------------------------------------------------
// Reduce: Gaussian PoU over the SAME window predicate + hard-BC ansatz.
// ---------------------------------------------------------------------------
__global__ __launch_bounds__(256)
void fbpinn_reduce_kernel(const float* __restrict__ X, float* __restrict__ out) {
    const int n = blockIdx.x * 256 + threadIdx.x;
    const float x = X[n];
    const int b = bin_of(x);
    const float inv_sigma = 64.0f / 1.5f;
    float num = 0.0f, den = 0.0f;
#pragma unroll 1
    for (int s = 0; s < 64; s++) {
        int lo, hi;
        window_of(s, lo, hi);
        if (b >= lo && b <= hi) {
            float tt = (x - (float)s * (1.0f / 63.0f)) * inv_sigma;
            float r = __expf(-0.5f * tt * tt);
            num = fmaf(r, g_u[s * NPTS + n], num);
            den += r;
        }
    }
    out[n] = tanh_acc(5.0f * x) * (num / den);
}

// ---------------------------------------------------------------------------
// Inputs: x, W0, b0, W1, b1, W2, b2, W3, b3. Output fp32 [65536].
// ---------------------------------------------------------------------------
extern "C" void kernel_launch(void* const* d_in, const int* in_sizes, int n_in,
                              void* d_out, int out_size) {
    const float* X  = (const float*)d_in[0];
    const float* W0 = (const float*)d_in[1];
    const float* B0 = (const float*)d_in[2];
    const float* W1 = (const float*)d_in[3];
    const float* B1 = (const float*)d_in[4];
    const float* W2 = (const float*)d_in[5];
    const float* B2 = (const float*)d_in[6];
    const float* W3 = (const float*)d_in[7];
    const float* B3 = (const float*)d_in[8];
    float* out = (float*)d_out;

    cudaFuncSetAttribute(fbpinn_mlp, cudaFuncAttributeMaxDynamicSharedMemorySize,
                         (int)sizeof(SMem));

    const int prep_elems = 2 * NSUB * 4096;
    prep_weights<<<(prep_elems + 255) / 256, 256>>>(W1, W2);
    zero_counters<<<1, 64>>>();
    bin_points<<<NPTS / 256, 256>>>(X);
    dim3 grid(GRIDX, NSUB);
    fbpinn_mlp<<<grid, TPB, sizeof(SMem)>>>(X, W0, B0, B1, B2, W3, B3);
    fbpinn_reduce_kernel<<<NPTS / 256, 256>>>(X, out);
}

// round 12
// speedup vs baseline: 1.0727x; 1.0727x over previous
#include <cuda_runtime.h>
#include <cstdint>

#define NSUB  64
#define NPTS  65536
#define TPB   256         // 8 warps; each warp owns 32 of the tile's 256 points
#define TILES 8           // 256-pt tiles per CTA
#define GRIDX 9           // slots per subdomain = 9*8*256 = 18432 (max ~16900)
#define STR   68          // H row stride (floats): conflict-free frag access
#define RWIN  0.1171875f  // 7.5/64 — PoU window radius (tail < ~5e-5 rel)

// Static device scratch (no allocation).
__device__ float    g_u[NSUB * NPTS];
// Fragment-packed tf32 weights: [l][s][ ((kk*4+c)*32 + lane)*4 + i ]
__device__ uint32_t gBp[2][NSUB][4096];
__device__ int      g_bin_cnt[64];
__device__ int      g_bin_idx[64][NPTS];

// ---------------------------------------------------------------------------
// Scalar helpers
// ---------------------------------------------------------------------------
__device__ __forceinline__ float tanh_hw(float x) {
    float r; asm("tanh.approx.f32 %0, %1;" : "=f"(r) : "f"(x)); return r;
}
__device__ __forceinline__ float tanh_acc(float x) {
    float e; asm("ex2.approx.f32 %0, %1;" : "=f"(e) : "f"(x * 2.8853900817779268f));
    float r; asm("rcp.approx.f32 %0, %1;" : "=f"(r) : "f"(e + 1.0f));
    return fmaf(-2.0f, r, 1.0f);
}
__device__ __forceinline__ uint32_t f2tf32(float f) {
    uint32_t r; asm("cvt.rna.tf32.f32 %0, %1;" : "=r"(r) : "f"(f)); return r;
}

// PoU bin window — single definition shared by MLP (writer) and reduce (reader).
__device__ __forceinline__ void window_of(int s, int& lo, int& hi) {
    const float c = (float)s * (1.0f / 63.0f);
    int l = (int)floorf((c - RWIN) * 64.0f);
    int h = (int)floorf((c + RWIN) * 64.0f);
    lo = l < 0 ? 0 : l;
    hi = h > 63 ? 63 : h;
}
__device__ __forceinline__ int bin_of(float x) {
    int b = (int)(x * 64.0f);
    return b < 0 ? 0 : (b > 63 ? 63 : b);
}

// mma.sync m16n8k8 tf32 (baseline PTX, tensor pipe). A operands carry raw f32
// bits: tf32 HMMA reads only the top 19 bits (truncation, err ~2^-11).
__device__ __forceinline__ void mma8(float& d0, float& d1, float& d2, float& d3,
                                     uint32_t a0, uint32_t a1, uint32_t a2, uint32_t a3,
                                     uint32_t b0, uint32_t b1) {
    asm volatile(
        "mma.sync.aligned.m16n8k8.row.col.f32.tf32.tf32.f32 "
        "{%0,%1,%2,%3}, {%4,%5,%6,%7}, {%8,%9}, {%0,%1,%2,%3};"
        : "+f"(d0), "+f"(d1), "+f"(d2), "+f"(d3)
        : "r"(a0), "r"(a1), "r"(a2), "r"(a3), "r"(b0), "r"(b1));
}

// ---------------------------------------------------------------------------
// Prep: COALESCED reads (thread i reads element i), scattered fire-and-forget
// stores into the fragment-packed layout. Also zeroes bin counters (this
// kernel is stream-ordered before bin_points).
// ---------------------------------------------------------------------------
__global__ void prep_weights(const float* __restrict__ W1,
                             const float* __restrict__ W2) {
    const int i = blockIdx.x * 256 + threadIdx.x;          // over 2*64*4096
    if (blockIdx.x == 0 && threadIdx.x < 64) g_bin_cnt[threadIdx.x] = 0;
    if (i >= 2 * NSUB * 4096) return;
    const int l = i >> 18;                // layer
    const int r = i & 262143;             // s*4096 + n*64 + k
    const int s = r >> 12;
    const int n = (r >> 6) & 63;
    const int k = r & 63;
    // inverse fragment map: lane=(g,t), chunk c, slot ii
    const int nt = n >> 3, g = n & 7;
    const int kk = k >> 3, t = k & 3, wh = (k >> 2) & 1;
    const int j  = wh * 8 + nt;           // 0..15
    const int c  = j >> 2, ii = j & 3;
    const int lane = g * 4 + t;
    const int q  = ((kk * 4 + c) * 32 + lane) * 4 + ii;
    const float v = l ? W2[r] : W1[r];
    gBp[l][s][q] = f2tf32(v);
}
__global__ void bin_points(const float* __restrict__ X) {
    const int n = blockIdx.x * 256 + threadIdx.x;
    const int b = bin_of(X[n]);
    const int p = atomicAdd(&g_bin_cnt[b], 1);
    g_bin_idx[b][p] = n;
}

// ---------------------------------------------------------------------------
// Shared memory (~103 KB -> 2 CTAs/SM; 8 warps/CTA -> 16 warps/SM = 4/SMSP).
// Regs capped at 128 by launch_bounds (R10 measured exactly 128 -> no spill).
// ---------------------------------------------------------------------------
struct __align__(16) SMem {
    uint32_t Bp1[4096];            // 16 KB fragment-packed W1
    uint32_t Bp2[4096];            // 16 KB fragment-packed W2
    uint32_t H[8][32 * STR];       // per-warp activations (8 warps)
    float w0[64], b0[64], b1[64], b2[64], w3[64];
    float b3;
    int cum[24];
};

__device__ __forceinline__ int slot_to_n(const int* __restrict__ cum, int nb,
                                         int lo, int slot) {
    int j = 0;
#pragma unroll 1
    while (j + 1 < nb && slot >= cum[j + 1]) j++;
    return g_bin_idx[lo + j][slot - cum[j]];
}

// ---------------------------------------------------------------------------
// Main kernel. Fragment maps (m16n8k8, g = lane>>2, t = lane&3):
//   A: a0=(g,t) a1=(g+8,t) a2=(g,t+4) a3=(g+8,t+4)
//   B (packed): u0..u3 per kk -> bv0[nt], bv1[nt]
//   D: c0=(g,2t) c1=(g,2t+1) c2=(g+8,2t) c3=(g+8,2t+1)
// grid = (GRIDX, NSUB): CTA covers TILES x 256 slots of s's window list.
// ---------------------------------------------------------------------------
__global__ __launch_bounds__(TPB, 2)
void fbpinn_mlp(const float* __restrict__ X,
                const float* __restrict__ W0g, const float* __restrict__ B0g,
                const float* __restrict__ B1g, const float* __restrict__ B2g,
                const float* __restrict__ W3g, const float* __restrict__ B3g) {
    extern __shared__ char smraw[];
    SMem* sm = (SMem*)smraw;

    const int s    = blockIdx.y;
    const int tid  = threadIdx.x;
    const int wid  = tid >> 5;
    const int lane = tid & 31;
    const int g    = lane >> 2;
    const int t    = lane & 3;
    const int wb   = wid * 32;

    int lo, hi;
    window_of(s, lo, hi);
    const int nb = hi - lo + 1;

    if (tid < nb) sm->cum[tid + 1] = g_bin_cnt[lo + tid];
    if (tid == 0) sm->cum[0] = 0;
    __syncthreads();
    if (tid == 0) {
        int a = 0;
#pragma unroll 1
        for (int j = 1; j <= nb; j++) { a += sm->cum[j]; sm->cum[j] = a; }
    }
    __syncthreads();
    const int total = sm->cum[nb];
    if (blockIdx.x * (TILES * TPB) >= total) return;

    // cooperative smem fill: B tiles (coalesced uint4) + params
    {
        const uint4* s1 = (const uint4*)&gBp[0][s][0];
        const uint4* s2 = (const uint4*)&gBp[1][s][0];
        uint4* d1 = (uint4*)sm->Bp1;
        uint4* d2 = (uint4*)sm->Bp2;
        for (int i = tid; i < 1024; i += TPB) { d1[i] = s1[i]; d2[i] = s2[i]; }
        if (tid < 64) {
            sm->w0[tid] = W0g[s * 64 + tid];
            sm->b0[tid] = B0g[s * 64 + tid];
            sm->b1[tid] = B1g[s * 64 + tid];
            sm->b2[tid] = B2g[s * 64 + tid];
            sm->w3[tid] = W3g[s * 64 + tid];
        }
        if (tid == 64) sm->b3 = B3g[s];
    }
    __syncthreads();

    const float b3v = sm->b3;
    uint32_t* Hu = sm->H[wid];
    const uint4* bp1 = (const uint4*)sm->Bp1;
    const uint4* bp2 = (const uint4*)sm->Bp2;
    float acc[8][2][4];

#pragma unroll 1
    for (int tile = 0; tile < TILES; tile++) {
        const int tb = (blockIdx.x * TILES + tile) * TPB;
        if (tb >= total) break;

        const int r0 = tb + wb + g, r1 = r0 + 8, r2 = r0 + 16, r3 = r0 + 24;
        int n0 = -1, n1 = -1, n2 = -1, n3 = -1;
        float x0 = 0.f, x1 = 0.f, x2 = 0.f, x3 = 0.f;
        if (r0 < total) { n0 = slot_to_n(sm->cum, nb, lo, r0); x0 = X[n0]; }
        if (r1 < total) { n1 = slot_to_n(sm->cum, nb, lo, r1); x1 = X[n1]; }
        if (r2 < total) { n2 = slot_to_n(sm->cum, nb, lo, r2); x2 = X[n2]; }
        if (r3 < total) { n3 = slot_to_n(sm->cum, nb, lo, r3); x3 = X[n3]; }

        // ================= Layer 1 (A built on the fly from layer 0) ========
#pragma unroll
        for (int nt = 0; nt < 8; nt++) {
            const float2 bb = *(const float2*)&sm->b1[nt * 8 + 2 * t];
#pragma unroll
            for (int mt = 0; mt < 2; mt++) {
                acc[nt][mt][0] = bb.x; acc[nt][mt][1] = bb.y;
                acc[nt][mt][2] = bb.x; acc[nt][mt][3] = bb.y;
            }
        }
#pragma unroll
        for (int kk = 0; kk < 8; kk++) {
            const int k0 = kk * 8;
            const float wc0 = sm->w0[k0 + t],     bc0 = sm->b0[k0 + t];
            const float wc1 = sm->w0[k0 + t + 4], bc1 = sm->b0[k0 + t + 4];
            uint32_t a0[4], a1[4];
            a0[0] = __float_as_uint(tanh_hw(fmaf(wc0, x0, bc0)));
            a0[1] = __float_as_uint(tanh_hw(fmaf(wc0, x1, bc0)));
            a0[2] = __float_as_uint(tanh_hw(fmaf(wc1, x0, bc1)));
            a0[3] = __float_as_uint(tanh_hw(fmaf(wc1, x1, bc1)));
            a1[0] = __float_as_uint(tanh_hw(fmaf(wc0, x2, bc0)));
            a1[1] = __float_as_uint(tanh_hw(fmaf(wc0, x3, bc0)));
            a1[2] = __float_as_uint(tanh_hw(fmaf(wc1, x2, bc1)));
            a1[3] = __float_as_uint(tanh_hw(fmaf(wc1, x3, bc1)));
            // packed B fragments: 4 x LDS.128, conflict-free
            const uint4 u0 = bp1[(kk * 4 + 0) * 32 + lane];
            const uint4 u1 = bp1[(kk * 4 + 1) * 32 + lane];
            const uint4 u2 = bp1[(kk * 4 + 2) * 32 + lane];
            const uint4 u3 = bp1[(kk * 4 + 3) * 32 + lane];
            const uint32_t bv0[8] = {u0.x, u0.y, u0.z, u0.w, u1.x, u1.y, u1.z, u1.w};
            const uint32_t bv1[8] = {u2.x, u2.y, u2.z, u2.w, u3.x, u3.y, u3.z, u3.w};
#pragma unroll
            for (int nt = 0; nt < 8; nt++) {
                mma8(acc[nt][0][0], acc[nt][0][1], acc[nt][0][2], acc[nt][0][3],
                     a0[0], a0[1], a0[2], a0[3], bv0[nt], bv1[nt]);
                mma8(acc[nt][1][0], acc[nt][1][1], acc[nt][1][2], acc[nt][1][3],
                     a1[0], a1[1], a1[2], a1[3], bv0[nt], bv1[nt]);
            }
        }

        // epilogue 1: tanh -> raw f32 bits -> per-warp H
        __syncwarp();
#pragma unroll
        for (int nt = 0; nt < 8; nt++) {
#pragma unroll
            for (int mt = 0; mt < 2; mt++) {
                uint2 lov, hiv;
                lov.x = __float_as_uint(tanh_hw(acc[nt][mt][0]));
                lov.y = __float_as_uint(tanh_hw(acc[nt][mt][1]));
                hiv.x = __float_as_uint(tanh_hw(acc[nt][mt][2]));
                hiv.y = __float_as_uint(tanh_hw(acc[nt][mt][3]));
                *(uint2*)&Hu[(mt * 16 + g) * STR + nt * 8 + 2 * t]     = lov;
                *(uint2*)&Hu[(mt * 16 + g + 8) * STR + nt * 8 + 2 * t] = hiv;
            }
        }
        __syncwarp();

        // ================= Layer 2 (A from H) ===============================
#pragma unroll
        for (int nt = 0; nt < 8; nt++) {
            const float2 bb = *(const float2*)&sm->b2[nt * 8 + 2 * t];
#pragma unroll
            for (int mt = 0; mt < 2; mt++) {
                acc[nt][mt][0] = bb.x; acc[nt][mt][1] = bb.y;
                acc[nt][mt][2] = bb.x; acc[nt][mt][3] = bb.y;
            }
        }
#pragma unroll
        for (int kk = 0; kk < 8; kk++) {
            const int k0 = kk * 8;
            uint32_t a0[4], a1[4];
            a0[0] = Hu[(g) * STR + k0 + t];
            a0[1] = Hu[(g + 8) * STR + k0 + t];
            a0[2] = Hu[(g) * STR + k0 + t + 4];
            a0[3] = Hu[(g + 8) * STR + k0 + t + 4];
            a1[0] = Hu[(g + 16) * STR + k0 + t];
            a1[1] = Hu[(g + 24) * STR + k0 + t];
            a1[2] = Hu[(g + 16) * STR + k0 + t + 4];
            a1[3] = Hu[(g + 24) * STR + k0 + t + 4];
            const uint4 u0 = bp2[(kk * 4 + 0) * 32 + lane];
            const uint4 u1 = bp2[(kk * 4 + 1) * 32 + lane];
            const uint4 u2 = bp2[(kk * 4 + 2) * 32 + lane];
            const uint4 u3 = bp2[(kk * 4 + 3) * 32 + lane];
            const uint32_t bv0[8] = {u0.x, u0.y, u0.z, u0.w, u1.x, u1.y, u1.z, u1.w};
            const uint32_t bv1[8] = {u2.x, u2.y, u2.z, u2.w, u3.x, u3.y, u3.z, u3.w};
#pragma unroll
            for (int nt = 0; nt < 8; nt++) {
                mma8(acc[nt][0][0], acc[nt][0][1], acc[nt][0][2], acc[nt][0][3],
                     a0[0], a0[1], a0[2], a0[3], bv0[nt], bv1[nt]);
                mma8(acc[nt][1][0], acc[nt][1][1], acc[nt][1][2], acc[nt][1][3],
                     a1[0], a1[1], a1[2], a1[3], bv0[nt], bv1[nt]);
            }
        }

        // ===== output layer (fp32): u[row] = b3 + sum_n w3[n]*tanh(acc) =====
        {
            float u0 = 0.f, u1 = 0.f, u2 = 0.f, u3 = 0.f;
#pragma unroll
            for (int nt = 0; nt < 8; nt++) {
                const float2 w3p = *(const float2*)&sm->w3[nt * 8 + 2 * t];
                u0 = fmaf(w3p.x, tanh_hw(acc[nt][0][0]), u0);
                u0 = fmaf(w3p.y, tanh_hw(acc[nt][0][1]), u0);
                u1 = fmaf(w3p.x, tanh_hw(acc[nt][0][2]), u1);
                u1 = fmaf(w3p.y, tanh_hw(acc[nt][0][3]), u1);
                u2 = fmaf(w3p.x, tanh_hw(acc[nt][1][0]), u2);
                u2 = fmaf(w3p.y, tanh_hw(acc[nt][1][1]), u2);
                u3 = fmaf(w3p.x, tanh_hw(acc[nt][1][2]), u3);
                u3 = fmaf(w3p.y, tanh_hw(acc[nt][1][3]), u3);
            }
#pragma unroll
            for (int d = 1; d < 4; d <<= 1) {
                u0 += __shfl_xor_sync(0xffffffffu, u0, d);
                u1 += __shfl_xor_sync(0xffffffffu, u1, d);
                u2 += __shfl_xor_sync(0xffffffffu, u2, d);
                u3 += __shfl_xor_sync(0xffffffffu, u3, d);
            }
            if (t == 0) {
                float* up = g_u + s * NPTS;
                if (n0 >= 0) up[n0] = u0 + b3v;
                if (n1 >= 0) up[n1] = u1 + b3v;
                if (n2 >= 0) up[n2] = u2 + b3v;
                if (n3 >= 0) up[n3] = u3 + b3v;
            }
        }
    }
}

// ---------------------------------------------------------------------------
// Reduce: Gaussian PoU over the SAME window predicate + hard-BC ansatz.
// ---------------------------------------------------------------------------
__global__ __launch_bounds__(256)
void fbpinn_reduce_kernel(const float* __restrict__ X, float* __restrict__ out) {
    const int n = blockIdx.x * 256 + threadIdx.x;
    const float x = X[n];
    const int b = bin_of(x);
    const float inv_sigma = 64.0f / 1.5f;
    float num = 0.0f, den = 0.0f;
#pragma unroll 1
    for (int s = 0; s < 64; s++) {
        int lo, hi;
        window_of(s, lo, hi);
        if (b >= lo && b <= hi) {
            float tt = (x - (float)s * (1.0f / 63.0f)) * inv_sigma;
            float r = __expf(-0.5f * tt * tt);
            num = fmaf(r, g_u[s * NPTS + n], num);
            den += r;
        }
    }
    out[n] = tanh_acc(5.0f * x) * (num / den);
}

// ---------------------------------------------------------------------------
// Inputs: x, W0, b0, W1, b1, W2, b2, W3, b3. Output fp32 [65536].
// ---------------------------------------------------------------------------
extern "C" void kernel_launch(void* const* d_in, const int* in_sizes, int n_in,
                              void* d_out, int out_size) {
    const float* X  = (const float*)d_in[0];
    const float* W0 = (const float*)d_in[1];
    const float* B0 = (const float*)d_in[2];
    const float* W1 = (const float*)d_in[3];
    const float* B1 = (const float*)d_in[4];
    const float* W2 = (const float*)d_in[5];
    const float* B2 = (const float*)d_in[6];
    const float* W3 = (const float*)d_in[7];
    const float* B3 = (const float*)d_in[8];
    float* out = (float*)d_out;

    cudaFuncSetAttribute(fbpinn_mlp, cudaFuncAttributeMaxDynamicSharedMemorySize,
                         (int)sizeof(SMem));

    const int prep_elems = 2 * NSUB * 4096;
    prep_weights<<<(prep_elems + 255) / 256, 256>>>(W1, W2);
    bin_points<<<NPTS / 256, 256>>>(X);
    dim3 grid(GRIDX, NSUB);
    fbpinn_mlp<<<grid, TPB, sizeof(SMem)>>>(X, W0, B0, B1, B2, W3, B3);
    fbpinn_reduce_kernel<<<NPTS / 256, 256>>>(X, out);
}

// round 13
// speedup vs baseline: 1.1521x; 1.0740x over previous
#include <cuda_runtime.h>
#include <cstdint>

#define NSUB  64
#define NPTS  65536
#define TPB   256         // 8 warps; each warp owns 32 of the tile's 256 points
#define TILES 8           // 256-pt tiles per CTA
#define GRIDX 9           // slots per subdomain = 9*8*256 = 18432 (max ~16900)
#define STR   68          // H row stride (floats): conflict-free frag access
#define RWIN  0.1171875f  // 7.5/64 — PoU window radius (tail < ~5e-5 rel)

// Static device scratch (no allocation).
__device__ float    g_u[NSUB * NPTS];
// Fragment-packed tf32 weights: [l][s][ ((kk*4+c)*32 + lane)*4 + i ]
__device__ uint32_t gBp[2][NSUB][4096];
__device__ int      g_bin_cnt[64];
__device__ int      g_bin_idx[64][NPTS];

// ---------------------------------------------------------------------------
// Scalar helpers
// ---------------------------------------------------------------------------
__device__ __forceinline__ float tanh_hw(float x) {
    float r; asm("tanh.approx.f32 %0, %1;" : "=f"(r) : "f"(x)); return r;
}
__device__ __forceinline__ float tanh_acc(float x) {
    float e; asm("ex2.approx.f32 %0, %1;" : "=f"(e) : "f"(x * 2.8853900817779268f));
    float r; asm("rcp.approx.f32 %0, %1;" : "=f"(r) : "f"(e + 1.0f));
    return fmaf(-2.0f, r, 1.0f);
}
__device__ __forceinline__ uint32_t f2tf32(float f) {
    uint32_t r; asm("cvt.rna.tf32.f32 %0, %1;" : "=r"(r) : "f"(f)); return r;
}

// PoU bin window — single definition shared by MLP (writer) and reduce (reader).
__device__ __forceinline__ void window_of(int s, int& lo, int& hi) {
    const float c = (float)s * (1.0f / 63.0f);
    int l = (int)floorf((c - RWIN) * 64.0f);
    int h = (int)floorf((c + RWIN) * 64.0f);
    lo = l < 0 ? 0 : l;
    hi = h > 63 ? 63 : h;
}
__device__ __forceinline__ int bin_of(float x) {
    int b = (int)(x * 64.0f);
    return b < 0 ? 0 : (b > 63 ? 63 : b);
}

// mma.sync m16n8k8 tf32 (baseline PTX, tensor pipe). A operands carry raw f32
// bits: tf32 HMMA reads only the top 19 bits (truncation, err ~2^-11).
__device__ __forceinline__ void mma8(float& d0, float& d1, float& d2, float& d3,
                                     uint32_t a0, uint32_t a1, uint32_t a2, uint32_t a3,
                                     uint32_t b0, uint32_t b1) {
    asm volatile(
        "mma.sync.aligned.m16n8k8.row.col.f32.tf32.tf32.f32 "
        "{%0,%1,%2,%3}, {%4,%5,%6,%7}, {%8,%9}, {%0,%1,%2,%3};"
        : "+f"(d0), "+f"(d1), "+f"(d2), "+f"(d3)
        : "r"(a0), "r"(a1), "r"(a2), "r"(a3), "r"(b0), "r"(b1));
}

// ---------------------------------------------------------------------------
// Prep: COALESCED reads, scattered fire-and-forget stores into the
// fragment-packed layout. Also zeroes bin counters (stream-ordered first).
// ---------------------------------------------------------------------------
__global__ void prep_weights(const float* __restrict__ W1,
                             const float* __restrict__ W2) {
    const int i = blockIdx.x * 256 + threadIdx.x;          // over 2*64*4096
    if (blockIdx.x == 0 && threadIdx.x < 64) g_bin_cnt[threadIdx.x] = 0;
    if (i >= 2 * NSUB * 4096) return;
    const int l = i >> 18;                // layer
    const int r = i & 262143;             // s*4096 + n*64 + k
    const int s = r >> 12;
    const int n = (r >> 6) & 63;
    const int k = r & 63;
    // inverse fragment map: lane=(g,t), chunk c, slot ii
    const int nt = n >> 3, g = n & 7;
    const int kk = k >> 3, t = k & 3, wh = (k >> 2) & 1;
    const int j  = wh * 8 + nt;           // 0..15
    const int c  = j >> 2, ii = j & 3;
    const int lane = g * 4 + t;
    const int q  = ((kk * 4 + c) * 32 + lane) * 4 + ii;
    const float v = l ? W2[r] : W1[r];
    gBp[l][s][q] = f2tf32(v);
}
__global__ void bin_points(const float* __restrict__ X) {
    const int n = blockIdx.x * 256 + threadIdx.x;
    const int b = bin_of(X[n]);
    const int p = atomicAdd(&g_bin_cnt[b], 1);
    g_bin_idx[b][p] = n;
}

// ---------------------------------------------------------------------------
// Shared memory (~103 KB -> 2 CTAs/SM; 8 warps/CTA -> 16 warps/SM = 4/SMSP).
// Regs capped at 128 by launch_bounds (R10 measured exactly 128 -> no spill).
// ---------------------------------------------------------------------------
struct __align__(16) SMem {
    uint32_t Bp1[4096];            // 16 KB fragment-packed W1
    uint32_t Bp2[4096];            // 16 KB fragment-packed W2
    uint32_t H[8][32 * STR];       // per-warp activations (8 warps)
    float w0[64], b0[64], b1[64], b2[64], w3[64];
    float b3;
    int cum[24];
};

__device__ __forceinline__ int slot_to_n(const int* __restrict__ cum, int nb,
                                         int lo, int slot) {
    int j = 0;
#pragma unroll 1
    while (j + 1 < nb && slot >= cum[j + 1]) j++;
    return g_bin_idx[lo + j][slot - cum[j]];
}

// ---------------------------------------------------------------------------
// Main kernel (identical to the 178us R12 config). Fragment maps (m16n8k8):
//   A: a0=(g,t) a1=(g+8,t) a2=(g,t+4) a3=(g+8,t+4)
//   B (packed): u0..u3 per kk -> bv0[nt], bv1[nt]
//   D: c0=(g,2t) c1=(g,2t+1) c2=(g+8,2t) c3=(g+8,2t+1)
// ---------------------------------------------------------------------------
__global__ __launch_bounds__(TPB, 2)
void fbpinn_mlp(const float* __restrict__ X,
                const float* __restrict__ W0g, const float* __restrict__ B0g,
                const float* __restrict__ B1g, const float* __restrict__ B2g,
                const float* __restrict__ W3g, const float* __restrict__ B3g) {
    extern __shared__ char smraw[];
    SMem* sm = (SMem*)smraw;

    const int s    = blockIdx.y;
    const int tid  = threadIdx.x;
    const int wid  = tid >> 5;
    const int lane = tid & 31;
    const int g    = lane >> 2;
    const int t    = lane & 3;
    const int wb   = wid * 32;

    int lo, hi;
    window_of(s, lo, hi);
    const int nb = hi - lo + 1;

    if (tid < nb) sm->cum[tid + 1] = g_bin_cnt[lo + tid];
    if (tid == 0) sm->cum[0] = 0;
    __syncthreads();
    if (tid == 0) {
        int a = 0;
#pragma unroll 1
        for (int j = 1; j <= nb; j++) { a += sm->cum[j]; sm->cum[j] = a; }
    }
    __syncthreads();
    const int total = sm->cum[nb];
    if (blockIdx.x * (TILES * TPB) >= total) return;

    // cooperative smem fill: B tiles (coalesced uint4) + params
    {
        const uint4* s1 = (const uint4*)&gBp[0][s][0];
        const uint4* s2 = (const uint4*)&gBp[1][s][0];
        uint4* d1 = (uint4*)sm->Bp1;
        uint4* d2 = (uint4*)sm->Bp2;
        for (int i = tid; i < 1024; i += TPB) { d1[i] = s1[i]; d2[i] = s2[i]; }
        if (tid < 64) {
            sm->w0[tid] = W0g[s * 64 + tid];
            sm->b0[tid] = B0g[s * 64 + tid];
            sm->b1[tid] = B1g[s * 64 + tid];
            sm->b2[tid] = B2g[s * 64 + tid];
            sm->w3[tid] = W3g[s * 64 + tid];
        }
        if (tid == 64) sm->b3 = B3g[s];
    }
    __syncthreads();

    const float b3v = sm->b3;
    uint32_t* Hu = sm->H[wid];
    const uint4* bp1 = (const uint4*)sm->Bp1;
    const uint4* bp2 = (const uint4*)sm->Bp2;
    float acc[8][2][4];

#pragma unroll 1
    for (int tile = 0; tile < TILES; tile++) {
        const int tb = (blockIdx.x * TILES + tile) * TPB;
        if (tb >= total) break;

        const int r0 = tb + wb + g, r1 = r0 + 8, r2 = r0 + 16, r3 = r0 + 24;
        int n0 = -1, n1 = -1, n2 = -1, n3 = -1;
        float x0 = 0.f, x1 = 0.f, x2 = 0.f, x3 = 0.f;
        if (r0 < total) { n0 = slot_to_n(sm->cum, nb, lo, r0); x0 = X[n0]; }
        if (r1 < total) { n1 = slot_to_n(sm->cum, nb, lo, r1); x1 = X[n1]; }
        if (r2 < total) { n2 = slot_to_n(sm->cum, nb, lo, r2); x2 = X[n2]; }
        if (r3 < total) { n3 = slot_to_n(sm->cum, nb, lo, r3); x3 = X[n3]; }

        // ================= Layer 1 (A built on the fly from layer 0) ========
#pragma unroll
        for (int nt = 0; nt < 8; nt++) {
            const float2 bb = *(const float2*)&sm->b1[nt * 8 + 2 * t];
#pragma unroll
            for (int mt = 0; mt < 2; mt++) {
                acc[nt][mt][0] = bb.x; acc[nt][mt][1] = bb.y;
                acc[nt][mt][2] = bb.x; acc[nt][mt][3] = bb.y;
            }
        }
#pragma unroll
        for (int kk = 0; kk < 8; kk++) {
            const int k0 = kk * 8;
            const float wc0 = sm->w0[k0 + t],     bc0 = sm->b0[k0 + t];
            const float wc1 = sm->w0[k0 + t + 4], bc1 = sm->b0[k0 + t + 4];
            uint32_t a0[4], a1[4];
            a0[0] = __float_as_uint(tanh_hw(fmaf(wc0, x0, bc0)));
            a0[1] = __float_as_uint(tanh_hw(fmaf(wc0, x1, bc0)));
            a0[2] = __float_as_uint(tanh_hw(fmaf(wc1, x0, bc1)));
            a0[3] = __float_as_uint(tanh_hw(fmaf(wc1, x1, bc1)));
            a1[0] = __float_as_uint(tanh_hw(fmaf(wc0, x2, bc0)));
            a1[1] = __float_as_uint(tanh_hw(fmaf(wc0, x3, bc0)));
            a1[2] = __float_as_uint(tanh_hw(fmaf(wc1, x2, bc1)));
            a1[3] = __float_as_uint(tanh_hw(fmaf(wc1, x3, bc1)));
            // packed B fragments: 4 x LDS.128, conflict-free
            const uint4 u0 = bp1[(kk * 4 + 0) * 32 + lane];
            const uint4 u1 = bp1[(kk * 4 + 1) * 32 + lane];
            const uint4 u2 = bp1[(kk * 4 + 2) * 32 + lane];
            const uint4 u3 = bp1[(kk * 4 + 3) * 32 + lane];
            const uint32_t bv0[8] = {u0.x, u0.y, u0.z, u0.w, u1.x, u1.y, u1.z, u1.w};
            const uint32_t bv1[8] = {u2.x, u2.y, u2.z, u2.w, u3.x, u3.y, u3.z, u3.w};
#pragma unroll
            for (int nt = 0; nt < 8; nt++) {
                mma8(acc[nt][0][0], acc[nt][0][1], acc[nt][0][2], acc[nt][0][3],
                     a0[0], a0[1], a0[2], a0[3], bv0[nt], bv1[nt]);
                mma8(acc[nt][1][0], acc[nt][1][1], acc[nt][1][2], acc[nt][1][3],
                     a1[0], a1[1], a1[2], a1[3], bv0[nt], bv1[nt]);
            }
        }

        // epilogue 1: tanh -> raw f32 bits -> per-warp H
        __syncwarp();
#pragma unroll
        for (int nt = 0; nt < 8; nt++) {
#pragma unroll
            for (int mt = 0; mt < 2; mt++) {
                uint2 lov, hiv;
                lov.x = __float_as_uint(tanh_hw(acc[nt][mt][0]));
                lov.y = __float_as_uint(tanh_hw(acc[nt][mt][1]));
                hiv.x = __float_as_uint(tanh_hw(acc[nt][mt][2]));
                hiv.y = __float_as_uint(tanh_hw(acc[nt][mt][3]));
                *(uint2*)&Hu[(mt * 16 + g) * STR + nt * 8 + 2 * t]     = lov;
                *(uint2*)&Hu[(mt * 16 + g + 8) * STR + nt * 8 + 2 * t] = hiv;
            }
        }
        __syncwarp();

        // ================= Layer 2 (A from H) ===============================
#pragma unroll
        for (int nt = 0; nt < 8; nt++) {
            const float2 bb = *(const float2*)&sm->b2[nt * 8 + 2 * t];
#pragma unroll
            for (int mt = 0; mt < 2; mt++) {
                acc[nt][mt][0] = bb.x; acc[nt][mt][1] = bb.y;
                acc[nt][mt][2] = bb.x; acc[nt][mt][3] = bb.y;
            }
        }
#pragma unroll
        for (int kk = 0; kk < 8; kk++) {
            const int k0 = kk * 8;
            uint32_t a0[4], a1[4];
            a0[0] = Hu[(g) * STR + k0 + t];
            a0[1] = Hu[(g + 8) * STR + k0 + t];
            a0[2] = Hu[(g) * STR + k0 + t + 4];
            a0[3] = Hu[(g + 8) * STR + k0 + t + 4];
            a1[0] = Hu[(g + 16) * STR + k0 + t];
            a1[1] = Hu[(g + 24) * STR + k0 + t];
            a1[2] = Hu[(g + 16) * STR + k0 + t + 4];
            a1[3] = Hu[(g + 24) * STR + k0 + t + 4];
            const uint4 u0 = bp2[(kk * 4 + 0) * 32 + lane];
            const uint4 u1 = bp2[(kk * 4 + 1) * 32 + lane];
            const uint4 u2 = bp2[(kk * 4 + 2) * 32 + lane];
            const uint4 u3 = bp2[(kk * 4 + 3) * 32 + lane];
            const uint32_t bv0[8] = {u0.x, u0.y, u0.z, u0.w, u1.x, u1.y, u1.z, u1.w};
            const uint32_t bv1[8] = {u2.x, u2.y, u2.z, u2.w, u3.x, u3.y, u3.z, u3.w};
#pragma unroll
            for (int nt = 0; nt < 8; nt++) {
                mma8(acc[nt][0][0], acc[nt][0][1], acc[nt][0][2], acc[nt][0][3],
                     a0[0], a0[1], a0[2], a0[3], bv0[nt], bv1[nt]);
                mma8(acc[nt][1][0], acc[nt][1][1], acc[nt][1][2], acc[nt][1][3],
                     a1[0], a1[1], a1[2], a1[3], bv0[nt], bv1[nt]);
            }
        }

        // ===== output layer (fp32): u[row] = b3 + sum_n w3[n]*tanh(acc) =====
        {
            float u0 = 0.f, u1 = 0.f, u2 = 0.f, u3 = 0.f;
#pragma unroll
            for (int nt = 0; nt < 8; nt++) {
                const float2 w3p = *(const float2*)&sm->w3[nt * 8 + 2 * t];
                u0 = fmaf(w3p.x, tanh_hw(acc[nt][0][0]), u0);
                u0 = fmaf(w3p.y, tanh_hw(acc[nt][0][1]), u0);
                u1 = fmaf(w3p.x, tanh_hw(acc[nt][0][2]), u1);
                u1 = fmaf(w3p.y, tanh_hw(acc[nt][0][3]), u1);
                u2 = fmaf(w3p.x, tanh_hw(acc[nt][1][0]), u2);
                u2 = fmaf(w3p.y, tanh_hw(acc[nt][1][1]), u2);
                u3 = fmaf(w3p.x, tanh_hw(acc[nt][1][2]), u3);
                u3 = fmaf(w3p.y, tanh_hw(acc[nt][1][3]), u3);
            }
#pragma unroll
            for (int d = 1; d < 4; d <<= 1) {
                u0 += __shfl_xor_sync(0xffffffffu, u0, d);
                u1 += __shfl_xor_sync(0xffffffffu, u1, d);
                u2 += __shfl_xor_sync(0xffffffffu, u2, d);
                u3 += __shfl_xor_sync(0xffffffffu, u3, d);
            }
            if (t == 0) {
                float* up = g_u + s * NPTS;
                if (n0 >= 0) up[n0] = u0 + b3v;
                if (n1 >= 0) up[n1] = u1 + b3v;
                if (n2 >= 0) up[n2] = u2 + b3v;
                if (n3 >= 0) up[n3] = u3 + b3v;
            }
        }
    }
}

// ---------------------------------------------------------------------------
// Reduce: per-bin contiguous s-range [smin[b], smax[b]] precomputed in smem
// from the SAME window_of as the writer (exact coverage match; ascending-s
// summation order identical to the old predicated loop -> bitwise-same output).
// Hot loop: ~16 iterations of FMA + ex2 + coalesced g_u load. No floorf/branch.
// ---------------------------------------------------------------------------
__global__ __launch_bounds__(256)
void fbpinn_reduce_kernel(const float* __restrict__ X, float* __restrict__ out) {
    __shared__ int ssmin[64], ssmax[64];
    const int tid = threadIdx.x;
    if (tid < 64) {
        int mn = 64, mx = -1;
#pragma unroll 1
        for (int s = 0; s < 64; s++) {
            int lo, hi;
            window_of(s, lo, hi);
            if (tid >= lo && tid <= hi) { if (s < mn) mn = s; if (s > mx) mx = s; }
        }
        ssmin[tid] = mn;
        ssmax[tid] = mx;
    }
    __syncthreads();

    const int n = blockIdx.x * 256 + tid;
    const float x = X[n];
    const int b = bin_of(x);
    const int s0 = ssmin[b], s1 = ssmax[b];
    const float inv_sigma = 64.0f / 1.5f;
    float num = 0.0f, den = 0.0f;
#pragma unroll 1
    for (int s = s0; s <= s1; s++) {
        const float tt = (x - (float)s * (1.0f / 63.0f)) * inv_sigma;
        const float r = __expf(-0.5f * tt * tt);
        num = fmaf(r, g_u[s * NPTS + n], num);
        den += r;
    }
    out[n] = tanh_acc(5.0f * x) * (num / den);
}

// ---------------------------------------------------------------------------
// Inputs: x, W0, b0, W1, b1, W2, b2, W3, b3. Output fp32 [65536].
// ---------------------------------------------------------------------------
extern "C" void kernel_launch(void* const* d_in, const int* in_sizes, int n_in,
                              void* d_out, int out_size) {
    const float* X  = (const float*)d_in[0];
    const float* W0 = (const float*)d_in[1];
    const float* B0 = (const float*)d_in[2];
    const float* W1 = (const float*)d_in[3];
    const float* B1 = (const float*)d_in[4];
    const float* W2 = (const float*)d_in[5];
    const float* B2 = (const float*)d_in[6];
    const float* W3 = (const float*)d_in[7];
    const float* B3 = (const float*)d_in[8];
    float* out = (float*)d_out;

    cudaFuncSetAttribute(fbpinn_mlp, cudaFuncAttributeMaxDynamicSharedMemorySize,
                         (int)sizeof(SMem));

    const int prep_elems = 2 * NSUB * 4096;
    prep_weights<<<(prep_elems + 255) / 256, 256>>>(W1, W2);
    bin_points<<<NPTS / 256, 256>>>(X);
    dim3 grid(GRIDX, NSUB);
    fbpinn_mlp<<<grid, TPB, sizeof(SMem)>>>(X, W0, B0, B1, B2, W3, B3);
    fbpinn_reduce_kernel<<<NPTS / 256, 256>>>(X, out);
}

// round 14
// speedup vs baseline: 1.2608x; 1.0943x over previous
#include <cuda_runtime.h>
#include <cstdint>

#define NSUB  64
#define NPTS  65536
#define TPB   256         // 8 warps; each warp owns 32 of the tile's 256 points
#define TILES 8           // 256-pt tiles per CTA
#define GRIDX 8           // slots per subdomain = 8*8*256 = 16384 (max ~14800)
#define STR   68          // H row stride (floats): conflict-free frag access
#define RWIN  0.1015625f  // 6.5/64 — PoU window radius (tail < ~1e-4 rel)

// Static device scratch (no allocation).
__device__ float    g_u[NSUB * NPTS];
// Fragment-packed tf32 weights: [l][s][ ((kk*4+c)*32 + lane)*4 + i ]
__device__ uint32_t gBp[2][NSUB][4096];
__device__ int      g_bin_cnt[64];
__device__ int      g_bin_idx[64][NPTS];

// ---------------------------------------------------------------------------
// Scalar helpers
// ---------------------------------------------------------------------------
__device__ __forceinline__ float tanh_hw(float x) {
    float r; asm("tanh.approx.f32 %0, %1;" : "=f"(r) : "f"(x)); return r;
}
__device__ __forceinline__ float tanh_acc(float x) {
    float e; asm("ex2.approx.f32 %0, %1;" : "=f"(e) : "f"(x * 2.8853900817779268f));
    float r; asm("rcp.approx.f32 %0, %1;" : "=f"(r) : "f"(e + 1.0f));
    return fmaf(-2.0f, r, 1.0f);
}
__device__ __forceinline__ uint32_t f2tf32(float f) {
    uint32_t r; asm("cvt.rna.tf32.f32 %0, %1;" : "=r"(r) : "f"(f)); return r;
}

// PoU bin window — single definition shared by MLP (writer) and reduce (reader).
__device__ __forceinline__ void window_of(int s, int& lo, int& hi) {
    const float c = (float)s * (1.0f / 63.0f);
    int l = (int)floorf((c - RWIN) * 64.0f);
    int h = (int)floorf((c + RWIN) * 64.0f);
    lo = l < 0 ? 0 : l;
    hi = h > 63 ? 63 : h;
}
__device__ __forceinline__ int bin_of(float x) {
    int b = (int)(x * 64.0f);
    return b < 0 ? 0 : (b > 63 ? 63 : b);
}

// mma.sync m16n8k8 tf32 (baseline PTX, tensor pipe). A operands carry raw f32
// bits: tf32 HMMA reads only the top 19 bits (truncation, err ~2^-11).
__device__ __forceinline__ void mma8(float& d0, float& d1, float& d2, float& d3,
                                     uint32_t a0, uint32_t a1, uint32_t a2, uint32_t a3,
                                     uint32_t b0, uint32_t b1) {
    asm volatile(
        "mma.sync.aligned.m16n8k8.row.col.f32.tf32.tf32.f32 "
        "{%0,%1,%2,%3}, {%4,%5,%6,%7}, {%8,%9}, {%0,%1,%2,%3};"
        : "+f"(d0), "+f"(d1), "+f"(d2), "+f"(d3)
        : "r"(a0), "r"(a1), "r"(a2), "r"(a3), "r"(b0), "r"(b1));
}

// ---------------------------------------------------------------------------
// Prep: COALESCED reads, scattered fire-and-forget stores into the
// fragment-packed layout. Also zeroes bin counters (stream-ordered first).
// ---------------------------------------------------------------------------
__global__ void prep_weights(const float* __restrict__ W1,
                             const float* __restrict__ W2) {
    const int i = blockIdx.x * 256 + threadIdx.x;          // over 2*64*4096
    if (blockIdx.x == 0 && threadIdx.x < 64) g_bin_cnt[threadIdx.x] = 0;
    if (i >= 2 * NSUB * 4096) return;
    const int l = i >> 18;                // layer
    const int r = i & 262143;             // s*4096 + n*64 + k
    const int s = r >> 12;
    const int n = (r >> 6) & 63;
    const int k = r & 63;
    // inverse fragment map: lane=(g,t), chunk c, slot ii
    const int nt = n >> 3, g = n & 7;
    const int kk = k >> 3, t = k & 3, wh = (k >> 2) & 1;
    const int j  = wh * 8 + nt;           // 0..15
    const int c  = j >> 2, ii = j & 3;
    const int lane = g * 4 + t;
    const int q  = ((kk * 4 + c) * 32 + lane) * 4 + ii;
    const float v = l ? W2[r] : W1[r];
    gBp[l][s][q] = f2tf32(v);
}
__global__ void bin_points(const float* __restrict__ X) {
    const int n = blockIdx.x * 256 + threadIdx.x;
    const int b = bin_of(X[n]);
    const int p = atomicAdd(&g_bin_cnt[b], 1);
    g_bin_idx[b][p] = n;
}

// ---------------------------------------------------------------------------
// Shared memory (~103 KB -> 2 CTAs/SM; 8 warps/CTA -> 16 warps/SM = 4/SMSP).
// Regs capped at 128 by launch_bounds (measured exactly 128 -> no spill).
// ---------------------------------------------------------------------------
struct __align__(16) SMem {
    uint32_t Bp1[4096];            // 16 KB fragment-packed W1
    uint32_t Bp2[4096];            // 16 KB fragment-packed W2
    uint32_t H[8][32 * STR];       // per-warp activations (8 warps)
    float w0[64], b0[64], b1[64], b2[64], w3[64];
    float b3;
    int cum[24];
};

__device__ __forceinline__ int slot_to_n(const int* __restrict__ cum, int nb,
                                         int lo, int slot) {
    int j = 0;
#pragma unroll 1
    while (j + 1 < nb && slot >= cum[j + 1]) j++;
    return g_bin_idx[lo + j][slot - cum[j]];
}

// ---------------------------------------------------------------------------
// Main kernel (R12/R13 proven config). Fragment maps (m16n8k8):
//   A: a0=(g,t) a1=(g+8,t) a2=(g,t+4) a3=(g+8,t+4)
//   B (packed): u0..u3 per kk -> bv0[nt], bv1[nt]
//   D: c0=(g,2t) c1=(g,2t+1) c2=(g+8,2t) c3=(g+8,2t+1)
// ---------------------------------------------------------------------------
__global__ __launch_bounds__(TPB, 2)
void fbpinn_mlp(const float* __restrict__ X,
                const float* __restrict__ W0g, const float* __restrict__ B0g,
                const float* __restrict__ B1g, const float* __restrict__ B2g,
                const float* __restrict__ W3g, const float* __restrict__ B3g) {
    extern __shared__ char smraw[];
    SMem* sm = (SMem*)smraw;

    const int s    = blockIdx.y;
    const int tid  = threadIdx.x;
    const int wid  = tid >> 5;
    const int lane = tid & 31;
    const int g    = lane >> 2;
    const int t    = lane & 3;
    const int wb   = wid * 32;

    int lo, hi;
    window_of(s, lo, hi);
    const int nb = hi - lo + 1;

    if (tid < nb) sm->cum[tid + 1] = g_bin_cnt[lo + tid];
    if (tid == 0) sm->cum[0] = 0;
    __syncthreads();
    if (tid == 0) {
        int a = 0;
#pragma unroll 1
        for (int j = 1; j <= nb; j++) { a += sm->cum[j]; sm->cum[j] = a; }
    }
    __syncthreads();
    const int total = sm->cum[nb];
    if (blockIdx.x * (TILES * TPB) >= total) return;

    // cooperative smem fill: B tiles (coalesced uint4) + params
    {
        const uint4* s1 = (const uint4*)&gBp[0][s][0];
        const uint4* s2 = (const uint4*)&gBp[1][s][0];
        uint4* d1 = (uint4*)sm->Bp1;
        uint4* d2 = (uint4*)sm->Bp2;
        for (int i = tid; i < 1024; i += TPB) { d1[i] = s1[i]; d2[i] = s2[i]; }
        if (tid < 64) {
            sm->w0[tid] = W0g[s * 64 + tid];
            sm->b0[tid] = B0g[s * 64 + tid];
            sm->b1[tid] = B1g[s * 64 + tid];
            sm->b2[tid] = B2g[s * 64 + tid];
            sm->w3[tid] = W3g[s * 64 + tid];
        }
        if (tid == 64) sm->b3 = B3g[s];
    }
    __syncthreads();

    const float b3v = sm->b3;
    uint32_t* Hu = sm->H[wid];
    const uint4* bp1 = (const uint4*)sm->Bp1;
    const uint4* bp2 = (const uint4*)sm->Bp2;
    float acc[8][2][4];

#pragma unroll 1
    for (int tile = 0; tile < TILES; tile++) {
        const int tb = (blockIdx.x * TILES + tile) * TPB;
        if (tb >= total) break;

        const int r0 = tb + wb + g, r1 = r0 + 8, r2 = r0 + 16, r3 = r0 + 24;
        int n0 = -1, n1 = -1, n2 = -1, n3 = -1;
        float x0 = 0.f, x1 = 0.f, x2 = 0.f, x3 = 0.f;
        if (r0 < total) { n0 = slot_to_n(sm->cum, nb, lo, r0); x0 = X[n0]; }
        if (r1 < total) { n1 = slot_to_n(sm->cum, nb, lo, r1); x1 = X[n1]; }
        if (r2 < total) { n2 = slot_to_n(sm->cum, nb, lo, r2); x2 = X[n2]; }
        if (r3 < total) { n3 = slot_to_n(sm->cum, nb, lo, r3); x3 = X[n3]; }

        // ================= Layer 1 (A built on the fly from layer 0) ========
#pragma unroll
        for (int nt = 0; nt < 8; nt++) {
            const float2 bb = *(const float2*)&sm->b1[nt * 8 + 2 * t];
#pragma unroll
            for (int mt = 0; mt < 2; mt++) {
                acc[nt][mt][0] = bb.x; acc[nt][mt][1] = bb.y;
                acc[nt][mt][2] = bb.x; acc[nt][mt][3] = bb.y;
            }
        }
#pragma unroll
        for (int kk = 0; kk < 8; kk++) {
            const int k0 = kk * 8;
            const float wc0 = sm->w0[k0 + t],     bc0 = sm->b0[k0 + t];
            const float wc1 = sm->w0[k0 + t + 4], bc1 = sm->b0[k0 + t + 4];
            uint32_t a0[4], a1[4];
            a0[0] = __float_as_uint(tanh_hw(fmaf(wc0, x0, bc0)));
            a0[1] = __float_as_uint(tanh_hw(fmaf(wc0, x1, bc0)));
            a0[2] = __float_as_uint(tanh_hw(fmaf(wc1, x0, bc1)));
            a0[3] = __float_as_uint(tanh_hw(fmaf(wc1, x1, bc1)));
            a1[0] = __float_as_uint(tanh_hw(fmaf(wc0, x2, bc0)));
            a1[1] = __float_as_uint(tanh_hw(fmaf(wc0, x3, bc0)));
            a1[2] = __float_as_uint(tanh_hw(fmaf(wc1, x2, bc1)));
            a1[3] = __float_as_uint(tanh_hw(fmaf(wc1, x3, bc1)));
            // packed B fragments: 4 x LDS.128, conflict-free
            const uint4 u0 = bp1[(kk * 4 + 0) * 32 + lane];
            const uint4 u1 = bp1[(kk * 4 + 1) * 32 + lane];
            const uint4 u2 = bp1[(kk * 4 + 2) * 32 + lane];
            const uint4 u3 = bp1[(kk * 4 + 3) * 32 + lane];
            const uint32_t bv0[8] = {u0.x, u0.y, u0.z, u0.w, u1.x, u1.y, u1.z, u1.w};
            const uint32_t bv1[8] = {u2.x, u2.y, u2.z, u2.w, u3.x, u3.y, u3.z, u3.w};
#pragma unroll
            for (int nt = 0; nt < 8; nt++) {
                mma8(acc[nt][0][0], acc[nt][0][1], acc[nt][0][2], acc[nt][0][3],
                     a0[0], a0[1], a0[2], a0[3], bv0[nt], bv1[nt]);
                mma8(acc[nt][1][0], acc[nt][1][1], acc[nt][1][2], acc[nt][1][3],
                     a1[0], a1[1], a1[2], a1[3], bv0[nt], bv1[nt]);
            }
        }

        // epilogue 1: tanh -> raw f32 bits -> per-warp H
        __syncwarp();
#pragma unroll
        for (int nt = 0; nt < 8; nt++) {
#pragma unroll
            for (int mt = 0; mt < 2; mt++) {
                uint2 lov, hiv;
                lov.x = __float_as_uint(tanh_hw(acc[nt][mt][0]));
                lov.y = __float_as_uint(tanh_hw(acc[nt][mt][1]));
                hiv.x = __float_as_uint(tanh_hw(acc[nt][mt][2]));
                hiv.y = __float_as_uint(tanh_hw(acc[nt][mt][3]));
                *(uint2*)&Hu[(mt * 16 + g) * STR + nt * 8 + 2 * t]     = lov;
                *(uint2*)&Hu[(mt * 16 + g + 8) * STR + nt * 8 + 2 * t] = hiv;
            }
        }
        __syncwarp();

        // ================= Layer 2 (A from H) ===============================
#pragma unroll
        for (int nt = 0; nt < 8; nt++) {
            const float2 bb = *(const float2*)&sm->b2[nt * 8 + 2 * t];
#pragma unroll
            for (int mt = 0; mt < 2; mt++) {
                acc[nt][mt][0] = bb.x; acc[nt][mt][1] = bb.y;
                acc[nt][mt][2] = bb.x; acc[nt][mt][3] = bb.y;
            }
        }
#pragma unroll
        for (int kk = 0; kk < 8; kk++) {
            const int k0 = kk * 8;
            uint32_t a0[4], a1[4];
            a0[0] = Hu[(g) * STR + k0 + t];
            a0[1] = Hu[(g + 8) * STR + k0 + t];
            a0[2] = Hu[(g) * STR + k0 + t + 4];
            a0[3] = Hu[(g + 8) * STR + k0 + t + 4];
            a1[0] = Hu[(g + 16) * STR + k0 + t];
            a1[1] = Hu[(g + 24) * STR + k0 + t];
            a1[2] = Hu[(g + 16) * STR + k0 + t + 4];
            a1[3] = Hu[(g + 24) * STR + k0 + t + 4];
            const uint4 u0 = bp2[(kk * 4 + 0) * 32 + lane];
            const uint4 u1 = bp2[(kk * 4 + 1) * 32 + lane];
            const uint4 u2 = bp2[(kk * 4 + 2) * 32 + lane];
            const uint4 u3 = bp2[(kk * 4 + 3) * 32 + lane];
            const uint32_t bv0[8] = {u0.x, u0.y, u0.z, u0.w, u1.x, u1.y, u1.z, u1.w};
            const uint32_t bv1[8] = {u2.x, u2.y, u2.z, u2.w, u3.x, u3.y, u3.z, u3.w};
#pragma unroll
            for (int nt = 0; nt < 8; nt++) {
                mma8(acc[nt][0][0], acc[nt][0][1], acc[nt][0][2], acc[nt][0][3],
                     a0[0], a0[1], a0[2], a0[3], bv0[nt], bv1[nt]);
                mma8(acc[nt][1][0], acc[nt][1][1], acc[nt][1][2], acc[nt][1][3],
                     a1[0], a1[1], a1[2], a1[3], bv0[nt], bv1[nt]);
            }
        }

        // ===== output layer (fp32): u[row] = b3 + sum_n w3[n]*tanh(acc) =====
        {
            float u0 = 0.f, u1 = 0.f, u2 = 0.f, u3 = 0.f;
#pragma unroll
            for (int nt = 0; nt < 8; nt++) {
                const float2 w3p = *(const float2*)&sm->w3[nt * 8 + 2 * t];
                u0 = fmaf(w3p.x, tanh_hw(acc[nt][0][0]), u0);
                u0 = fmaf(w3p.y, tanh_hw(acc[nt][0][1]), u0);
                u1 = fmaf(w3p.x, tanh_hw(acc[nt][0][2]), u1);
                u1 = fmaf(w3p.y, tanh_hw(acc[nt][0][3]), u1);
                u2 = fmaf(w3p.x, tanh_hw(acc[nt][1][0]), u2);
                u2 = fmaf(w3p.y, tanh_hw(acc[nt][1][1]), u2);
                u3 = fmaf(w3p.x, tanh_hw(acc[nt][1][2]), u3);
                u3 = fmaf(w3p.y, tanh_hw(acc[nt][1][3]), u3);
            }
#pragma unroll
            for (int d = 1; d < 4; d <<= 1) {
                u0 += __shfl_xor_sync(0xffffffffu, u0, d);
                u1 += __shfl_xor_sync(0xffffffffu, u1, d);
                u2 += __shfl_xor_sync(0xffffffffu, u2, d);
                u3 += __shfl_xor_sync(0xffffffffu, u3, d);
            }
            if (t == 0) {
                float* up = g_u + s * NPTS;
                if (n0 >= 0) up[n0] = u0 + b3v;
                if (n1 >= 0) up[n1] = u1 + b3v;
                if (n2 >= 0) up[n2] = u2 + b3v;
                if (n3 >= 0) up[n3] = u3 + b3v;
            }
        }
    }
}

// ---------------------------------------------------------------------------
// Reduce: per-bin contiguous s-range from the SAME window_of as the writer.
// s-loop unrolled x4 with independent accumulators -> 4 g_u loads in flight.
// ---------------------------------------------------------------------------
__global__ __launch_bounds__(256)
void fbpinn_reduce_kernel(const float* __restrict__ X, float* __restrict__ out) {
    __shared__ int ssmin[64], ssmax[64];
    const int tid = threadIdx.x;
    if (tid < 64) {
        int mn = 64, mx = -1;
#pragma unroll 1
        for (int s = 0; s < 64; s++) {
            int lo, hi;
            window_of(s, lo, hi);
            if (tid >= lo && tid <= hi) { if (s < mn) mn = s; if (s > mx) mx = s; }
        }
        ssmin[tid] = mn;
        ssmax[tid] = mx;
    }
    __syncthreads();

    const int n = blockIdx.x * 256 + tid;
    const float x = X[n];
    const int b = bin_of(x);
    const int s0 = ssmin[b], s1 = ssmax[b];
    const float inv_sigma = 64.0f / 1.5f;
    float nm0 = 0.f, nm1 = 0.f, nm2 = 0.f, nm3 = 0.f;
    float dn0 = 0.f, dn1 = 0.f, dn2 = 0.f, dn3 = 0.f;
    int s = s0;
#pragma unroll 1
    for (; s + 3 <= s1; s += 4) {
        const float g0 = g_u[(s + 0) * NPTS + n];
        const float g1 = g_u[(s + 1) * NPTS + n];
        const float g2 = g_u[(s + 2) * NPTS + n];
        const float g3 = g_u[(s + 3) * NPTS + n];
        float tt, r;
        tt = (x - (float)(s + 0) * (1.0f / 63.0f)) * inv_sigma;
        r = __expf(-0.5f * tt * tt); nm0 = fmaf(r, g0, nm0); dn0 += r;
        tt = (x - (float)(s + 1) * (1.0f / 63.0f)) * inv_sigma;
        r = __expf(-0.5f * tt * tt); nm1 = fmaf(r, g1, nm1); dn1 += r;
        tt = (x - (float)(s + 2) * (1.0f / 63.0f)) * inv_sigma;
        r = __expf(-0.5f * tt * tt); nm2 = fmaf(r, g2, nm2); dn2 += r;
        tt = (x - (float)(s + 3) * (1.0f / 63.0f)) * inv_sigma;
        r = __expf(-0.5f * tt * tt); nm3 = fmaf(r, g3, nm3); dn3 += r;
    }
#pragma unroll 1
    for (; s <= s1; s++) {
        const float tt = (x - (float)s * (1.0f / 63.0f)) * inv_sigma;
        const float r = __expf(-0.5f * tt * tt);
        nm0 = fmaf(r, g_u[s * NPTS + n], nm0); dn0 += r;
    }
    const float num = (nm0 + nm1) + (nm2 + nm3);
    const float den = (dn0 + dn1) + (dn2 + dn3);
    out[n] = tanh_acc(5.0f * x) * (num / den);
}

// ---------------------------------------------------------------------------
// Inputs: x, W0, b0, W1, b1, W2, b2, W3, b3. Output fp32 [65536].
// ---------------------------------------------------------------------------
extern "C" void kernel_launch(void* const* d_in, const int* in_sizes, int n_in,
                              void* d_out, int out_size) {
    const float* X  = (const float*)d_in[0];
    const float* W0 = (const float*)d_in[1];
    const float* B0 = (const float*)d_in[2];
    const float* W1 = (const float*)d_in[3];
    const float* B1 = (const float*)d_in[4];
    const float* W2 = (const float*)d_in[5];
    const float* B2 = (const float*)d_in[6];
    const float* W3 = (const float*)d_in[7];
    const float* B3 = (const float*)d_in[8];
    float* out = (float*)d_out;

    cudaFuncSetAttribute(fbpinn_mlp, cudaFuncAttributeMaxDynamicSharedMemorySize,
                         (int)sizeof(SMem));

    const int prep_elems = 2 * NSUB * 4096;
    prep_weights<<<(prep_elems + 255) / 256, 256>>>(W1, W2);
    bin_points<<<NPTS / 256, 256>>>(X);
    dim3 grid(GRIDX, NSUB);
    fbpinn_mlp<<<grid, TPB, sizeof(SMem)>>>(X, W0, B0, B1, B2, W3, B3);
    fbpinn_reduce_kernel<<<NPTS / 256, 256>>>(X, out);
}

// round 15
// speedup vs baseline: 1.4069x; 1.1158x over previous
#include <cuda_runtime.h>
#include <cstdint>

#define NSUB  64
#define NPTS  65536
#define TPB   256         // 8 warps; each warp owns 32 of the tile's 256 points
#define TILES 8           // 256-pt tiles per CTA
#define GRIDX 7           // slots per subdomain = 7*8*256 = 14336 (max ~12600)
#define STR   68          // H row stride (floats): conflict-free frag access
#define RWIN  0.0859375f  // 5.5/64 — PoU window radius (renormalized tail ~7e-3 mass,
                          // empirically ~7e-5 rel_err contribution per R13/R14 scaling)

// Static device scratch (no allocation).
__device__ float    g_u[NSUB * NPTS];
// Fragment-packed tf32 weights: [l][s][ ((kk*4+c)*32 + lane)*4 + i ]
__device__ uint32_t gBp[2][NSUB][4096];
__device__ int      g_bin_cnt[64];
__device__ int      g_bin_idx[64][NPTS];

// ---------------------------------------------------------------------------
// Scalar helpers
// ---------------------------------------------------------------------------
__device__ __forceinline__ float tanh_hw(float x) {
    float r; asm("tanh.approx.f32 %0, %1;" : "=f"(r) : "f"(x)); return r;
}
__device__ __forceinline__ float tanh_acc(float x) {
    float e; asm("ex2.approx.f32 %0, %1;" : "=f"(e) : "f"(x * 2.8853900817779268f));
    float r; asm("rcp.approx.f32 %0, %1;" : "=f"(r) : "f"(e + 1.0f));
    return fmaf(-2.0f, r, 1.0f);
}
__device__ __forceinline__ uint32_t f2tf32(float f) {
    uint32_t r; asm("cvt.rna.tf32.f32 %0, %1;" : "=r"(r) : "f"(f)); return r;
}

// PoU bin window — single definition shared by MLP (writer) and reduce (reader).
__device__ __forceinline__ void window_of(int s, int& lo, int& hi) {
    const float c = (float)s * (1.0f / 63.0f);
    int l = (int)floorf((c - RWIN) * 64.0f);
    int h = (int)floorf((c + RWIN) * 64.0f);
    lo = l < 0 ? 0 : l;
    hi = h > 63 ? 63 : h;
}
__device__ __forceinline__ int bin_of(float x) {
    int b = (int)(x * 64.0f);
    return b < 0 ? 0 : (b > 63 ? 63 : b);
}

// mma.sync m16n8k8 tf32 (baseline PTX, tensor pipe). A operands carry raw f32
// bits: tf32 HMMA reads only the top 19 bits (truncation, err ~2^-11).
__device__ __forceinline__ void mma8(float& d0, float& d1, float& d2, float& d3,
                                     uint32_t a0, uint32_t a1, uint32_t a2, uint32_t a3,
                                     uint32_t b0, uint32_t b1) {
    asm volatile(
        "mma.sync.aligned.m16n8k8.row.col.f32.tf32.tf32.f32 "
        "{%0,%1,%2,%3}, {%4,%5,%6,%7}, {%8,%9}, {%0,%1,%2,%3};"
        : "+f"(d0), "+f"(d1), "+f"(d2), "+f"(d3)
        : "r"(a0), "r"(a1), "r"(a2), "r"(a3), "r"(b0), "r"(b1));
}

// ---------------------------------------------------------------------------
// Prep: COALESCED reads, scattered fire-and-forget stores into the
// fragment-packed layout. Also zeroes bin counters (stream-ordered first).
// ---------------------------------------------------------------------------
__global__ void prep_weights(const float* __restrict__ W1,
                             const float* __restrict__ W2) {
    const int i = blockIdx.x * 256 + threadIdx.x;          // over 2*64*4096
    if (blockIdx.x == 0 && threadIdx.x < 64) g_bin_cnt[threadIdx.x] = 0;
    if (i >= 2 * NSUB * 4096) return;
    const int l = i >> 18;                // layer
    const int r = i & 262143;             // s*4096 + n*64 + k
    const int s = r >> 12;
    const int n = (r >> 6) & 63;
    const int k = r & 63;
    // inverse fragment map: lane=(g,t), chunk c, slot ii
    const int nt = n >> 3, g = n & 7;
    const int kk = k >> 3, t = k & 3, wh = (k >> 2) & 1;
    const int j  = wh * 8 + nt;           // 0..15
    const int c  = j >> 2, ii = j & 3;
    const int lane = g * 4 + t;
    const int q  = ((kk * 4 + c) * 32 + lane) * 4 + ii;
    const float v = l ? W2[r] : W1[r];
    gBp[l][s][q] = f2tf32(v);
}
__global__ void bin_points(const float* __restrict__ X) {
    const int n = blockIdx.x * 256 + threadIdx.x;
    const int b = bin_of(X[n]);
    const int p = atomicAdd(&g_bin_cnt[b], 1);
    g_bin_idx[b][p] = n;
}

// ---------------------------------------------------------------------------
// Shared memory (~103 KB -> 2 CTAs/SM; 8 warps/CTA -> 16 warps/SM = 4/SMSP).
// Regs capped at 128 by launch_bounds (measured exactly 128 -> no spill).
// ---------------------------------------------------------------------------
struct __align__(16) SMem {
    uint32_t Bp1[4096];            // 16 KB fragment-packed W1
    uint32_t Bp2[4096];            // 16 KB fragment-packed W2
    uint32_t H[8][32 * STR];       // per-warp activations (8 warps)
    float w0[64], b0[64], b1[64], b2[64], w3[64];
    float b3;
    int cum[24];
};

__device__ __forceinline__ int slot_to_n(const int* __restrict__ cum, int nb,
                                         int lo, int slot) {
    int j = 0;
#pragma unroll 1
    while (j + 1 < nb && slot >= cum[j + 1]) j++;
    return g_bin_idx[lo + j][slot - cum[j]];
}

// ---------------------------------------------------------------------------
// Main kernel (proven R12-R14 config). Fragment maps (m16n8k8):
//   A: a0=(g,t) a1=(g+8,t) a2=(g,t+4) a3=(g+8,t+4)
//   B (packed): u0..u3 per kk -> bv0[nt], bv1[nt]
//   D: c0=(g,2t) c1=(g,2t+1) c2=(g+8,2t) c3=(g+8,2t+1)
// ---------------------------------------------------------------------------
__global__ __launch_bounds__(TPB, 2)
void fbpinn_mlp(const float* __restrict__ X,
                const float* __restrict__ W0g, const float* __restrict__ B0g,
                const float* __restrict__ B1g, const float* __restrict__ B2g,
                const float* __restrict__ W3g, const float* __restrict__ B3g) {
    extern __shared__ char smraw[];
    SMem* sm = (SMem*)smraw;

    const int s    = blockIdx.y;
    const int tid  = threadIdx.x;
    const int wid  = tid >> 5;
    const int lane = tid & 31;
    const int g    = lane >> 2;
    const int t    = lane & 3;
    const int wb   = wid * 32;

    int lo, hi;
    window_of(s, lo, hi);
    const int nb = hi - lo + 1;

    if (tid < nb) sm->cum[tid + 1] = g_bin_cnt[lo + tid];
    if (tid == 0) sm->cum[0] = 0;
    __syncthreads();
    if (tid == 0) {
        int a = 0;
#pragma unroll 1
        for (int j = 1; j <= nb; j++) { a += sm->cum[j]; sm->cum[j] = a; }
    }
    __syncthreads();
    const int total = sm->cum[nb];
    if (blockIdx.x * (TILES * TPB) >= total) return;

    // cooperative smem fill: B tiles (coalesced uint4) + params
    {
        const uint4* s1 = (const uint4*)&gBp[0][s][0];
        const uint4* s2 = (const uint4*)&gBp[1][s][0];
        uint4* d1 = (uint4*)sm->Bp1;
        uint4* d2 = (uint4*)sm->Bp2;
        for (int i = tid; i < 1024; i += TPB) { d1[i] = s1[i]; d2[i] = s2[i]; }
        if (tid < 64) {
            sm->w0[tid] = W0g[s * 64 + tid];
            sm->b0[tid] = B0g[s * 64 + tid];
            sm->b1[tid] = B1g[s * 64 + tid];
            sm->b2[tid] = B2g[s * 64 + tid];
            sm->w3[tid] = W3g[s * 64 + tid];
        }
        if (tid == 64) sm->b3 = B3g[s];
    }
    __syncthreads();

    const float b3v = sm->b3;
    uint32_t* Hu = sm->H[wid];
    const uint4* bp1 = (const uint4*)sm->Bp1;
    const uint4* bp2 = (const uint4*)sm->Bp2;
    float acc[8][2][4];

#pragma unroll 1
    for (int tile = 0; tile < TILES; tile++) {
        const int tb = (blockIdx.x * TILES + tile) * TPB;
        if (tb >= total) break;

        const int r0 = tb + wb + g, r1 = r0 + 8, r2 = r0 + 16, r3 = r0 + 24;
        int n0 = -1, n1 = -1, n2 = -1, n3 = -1;
        float x0 = 0.f, x1 = 0.f, x2 = 0.f, x3 = 0.f;
        if (r0 < total) { n0 = slot_to_n(sm->cum, nb, lo, r0); x0 = X[n0]; }
        if (r1 < total) { n1 = slot_to_n(sm->cum, nb, lo, r1); x1 = X[n1]; }
        if (r2 < total) { n2 = slot_to_n(sm->cum, nb, lo, r2); x2 = X[n2]; }
        if (r3 < total) { n3 = slot_to_n(sm->cum, nb, lo, r3); x3 = X[n3]; }

        // ================= Layer 1 (A built on the fly from layer 0) ========
#pragma unroll
        for (int nt = 0; nt < 8; nt++) {
            const float2 bb = *(const float2*)&sm->b1[nt * 8 + 2 * t];
#pragma unroll
            for (int mt = 0; mt < 2; mt++) {
                acc[nt][mt][0] = bb.x; acc[nt][mt][1] = bb.y;
                acc[nt][mt][2] = bb.x; acc[nt][mt][3] = bb.y;
            }
        }
#pragma unroll
        for (int kk = 0; kk < 8; kk++) {
            const int k0 = kk * 8;
            const float wc0 = sm->w0[k0 + t],     bc0 = sm->b0[k0 + t];
            const float wc1 = sm->w0[k0 + t + 4], bc1 = sm->b0[k0 + t + 4];
            uint32_t a0[4], a1[4];
            a0[0] = __float_as_uint(tanh_hw(fmaf(wc0, x0, bc0)));
            a0[1] = __float_as_uint(tanh_hw(fmaf(wc0, x1, bc0)));
            a0[2] = __float_as_uint(tanh_hw(fmaf(wc1, x0, bc1)));
            a0[3] = __float_as_uint(tanh_hw(fmaf(wc1, x1, bc1)));
            a1[0] = __float_as_uint(tanh_hw(fmaf(wc0, x2, bc0)));
            a1[1] = __float_as_uint(tanh_hw(fmaf(wc0, x3, bc0)));
            a1[2] = __float_as_uint(tanh_hw(fmaf(wc1, x2, bc1)));
            a1[3] = __float_as_uint(tanh_hw(fmaf(wc1, x3, bc1)));
            // packed B fragments: 4 x LDS.128, conflict-free
            const uint4 u0 = bp1[(kk * 4 + 0) * 32 + lane];
            const uint4 u1 = bp1[(kk * 4 + 1) * 32 + lane];
            const uint4 u2 = bp1[(kk * 4 + 2) * 32 + lane];
            const uint4 u3 = bp1[(kk * 4 + 3) * 32 + lane];
            const uint32_t bv0[8] = {u0.x, u0.y, u0.z, u0.w, u1.x, u1.y, u1.z, u1.w};
            const uint32_t bv1[8] = {u2.x, u2.y, u2.z, u2.w, u3.x, u3.y, u3.z, u3.w};
#pragma unroll
            for (int nt = 0; nt < 8; nt++) {
                mma8(acc[nt][0][0], acc[nt][0][1], acc[nt][0][2], acc[nt][0][3],
                     a0[0], a0[1], a0[2], a0[3], bv0[nt], bv1[nt]);
                mma8(acc[nt][1][0], acc[nt][1][1], acc[nt][1][2], acc[nt][1][3],
                     a1[0], a1[1], a1[2], a1[3], bv0[nt], bv1[nt]);
            }
        }

        // epilogue 1: tanh -> raw f32 bits -> per-warp H
        __syncwarp();
#pragma unroll
        for (int nt = 0; nt < 8; nt++) {
#pragma unroll
            for (int mt = 0; mt < 2; mt++) {
                uint2 lov, hiv;
                lov.x = __float_as_uint(tanh_hw(acc[nt][mt][0]));
                lov.y = __float_as_uint(tanh_hw(acc[nt][mt][1]));
                hiv.x = __float_as_uint(tanh_hw(acc[nt][mt][2]));
                hiv.y = __float_as_uint(tanh_hw(acc[nt][mt][3]));
                *(uint2*)&Hu[(mt * 16 + g) * STR + nt * 8 + 2 * t]     = lov;
                *(uint2*)&Hu[(mt * 16 + g + 8) * STR + nt * 8 + 2 * t] = hiv;
            }
        }
        __syncwarp();

        // ================= Layer 2 (A from H) ===============================
#pragma unroll
        for (int nt = 0; nt < 8; nt++) {
            const float2 bb = *(const float2*)&sm->b2[nt * 8 + 2 * t];
#pragma unroll
            for (int mt = 0; mt < 2; mt++) {
                acc[nt][mt][0] = bb.x; acc[nt][mt][1] = bb.y;
                acc[nt][mt][2] = bb.x; acc[nt][mt][3] = bb.y;
            }
        }
#pragma unroll
        for (int kk = 0; kk < 8; kk++) {
            const int k0 = kk * 8;
            uint32_t a0[4], a1[4];
            a0[0] = Hu[(g) * STR + k0 + t];
            a0[1] = Hu[(g + 8) * STR + k0 + t];
            a0[2] = Hu[(g) * STR + k0 + t + 4];
            a0[3] = Hu[(g + 8) * STR + k0 + t + 4];
            a1[0] = Hu[(g + 16) * STR + k0 + t];
            a1[1] = Hu[(g + 24) * STR + k0 + t];
            a1[2] = Hu[(g + 16) * STR + k0 + t + 4];
            a1[3] = Hu[(g + 24) * STR + k0 + t + 4];
            const uint4 u0 = bp2[(kk * 4 + 0) * 32 + lane];
            const uint4 u1 = bp2[(kk * 4 + 1) * 32 + lane];
            const uint4 u2 = bp2[(kk * 4 + 2) * 32 + lane];
            const uint4 u3 = bp2[(kk * 4 + 3) * 32 + lane];
            const uint32_t bv0[8] = {u0.x, u0.y, u0.z, u0.w, u1.x, u1.y, u1.z, u1.w};
            const uint32_t bv1[8] = {u2.x, u2.y, u2.z, u2.w, u3.x, u3.y, u3.z, u3.w};
#pragma unroll
            for (int nt = 0; nt < 8; nt++) {
                mma8(acc[nt][0][0], acc[nt][0][1], acc[nt][0][2], acc[nt][0][3],
                     a0[0], a0[1], a0[2], a0[3], bv0[nt], bv1[nt]);
                mma8(acc[nt][1][0], acc[nt][1][1], acc[nt][1][2], acc[nt][1][3],
                     a1[0], a1[1], a1[2], a1[3], bv0[nt], bv1[nt]);
            }
        }

        // ===== output layer (fp32): u[row] = b3 + sum_n w3[n]*tanh(acc) =====
        {
            float u0 = 0.f, u1 = 0.f, u2 = 0.f, u3 = 0.f;
#pragma unroll
            for (int nt = 0; nt < 8; nt++) {
                const float2 w3p = *(const float2*)&sm->w3[nt * 8 + 2 * t];
                u0 = fmaf(w3p.x, tanh_hw(acc[nt][0][0]), u0);
                u0 = fmaf(w3p.y, tanh_hw(acc[nt][0][1]), u0);
                u1 = fmaf(w3p.x, tanh_hw(acc[nt][0][2]), u1);
                u1 = fmaf(w3p.y, tanh_hw(acc[nt][0][3]), u1);
                u2 = fmaf(w3p.x, tanh_hw(acc[nt][1][0]), u2);
                u2 = fmaf(w3p.y, tanh_hw(acc[nt][1][1]), u2);
                u3 = fmaf(w3p.x, tanh_hw(acc[nt][1][2]), u3);
                u3 = fmaf(w3p.y, tanh_hw(acc[nt][1][3]), u3);
            }
#pragma unroll
            for (int d = 1; d < 4; d <<= 1) {
                u0 += __shfl_xor_sync(0xffffffffu, u0, d);
                u1 += __shfl_xor_sync(0xffffffffu, u1, d);
                u2 += __shfl_xor_sync(0xffffffffu, u2, d);
                u3 += __shfl_xor_sync(0xffffffffu, u3, d);
            }
            if (t == 0) {
                float* up = g_u + s * NPTS;
                if (n0 >= 0) up[n0] = u0 + b3v;
                if (n1 >= 0) up[n1] = u1 + b3v;
                if (n2 >= 0) up[n2] = u2 + b3v;
                if (n3 >= 0) up[n3] = u3 + b3v;
            }
        }
    }
}

// ---------------------------------------------------------------------------
// Reduce: per-bin contiguous s-range from the SAME window_of as the writer.
// 128-thread CTAs (512 blocks -> ~3.5 CTAs/SM) + x4-unrolled s-loop:
// more in-flight g_u loads chip-wide for this latency-bound kernel.
// ---------------------------------------------------------------------------
__global__ __launch_bounds__(128)
void fbpinn_reduce_kernel(const float* __restrict__ X, float* __restrict__ out) {
    __shared__ int ssmin[64], ssmax[64];
    const int tid = threadIdx.x;
    if (tid < 64) {
        int mn = 64, mx = -1;
#pragma unroll 1
        for (int s = 0; s < 64; s++) {
            int lo, hi;
            window_of(s, lo, hi);
            if (tid >= lo && tid <= hi) { if (s < mn) mn = s; if (s > mx) mx = s; }
        }
        ssmin[tid] = mn;
        ssmax[tid] = mx;
    }
    __syncthreads();

    const int n = blockIdx.x * 128 + tid;
    const float x = X[n];
    const int b = bin_of(x);
    const int s0 = ssmin[b], s1 = ssmax[b];
    const float inv_sigma = 64.0f / 1.5f;
    float nm0 = 0.f, nm1 = 0.f, nm2 = 0.f, nm3 = 0.f;
    float dn0 = 0.f, dn1 = 0.f, dn2 = 0.f, dn3 = 0.f;
    int s = s0;
#pragma unroll 1
    for (; s + 3 <= s1; s += 4) {
        const float g0 = g_u[(s + 0) * NPTS + n];
        const float g1 = g_u[(s + 1) * NPTS + n];
        const float g2 = g_u[(s + 2) * NPTS + n];
        const float g3 = g_u[(s + 3) * NPTS + n];
        float tt, r;
        tt = (x - (float)(s + 0) * (1.0f / 63.0f)) * inv_sigma;
        r = __expf(-0.5f * tt * tt); nm0 = fmaf(r, g0, nm0); dn0 += r;
        tt = (x - (float)(s + 1) * (1.0f / 63.0f)) * inv_sigma;
        r = __expf(-0.5f * tt * tt); nm1 = fmaf(r, g1, nm1); dn1 += r;
        tt = (x - (float)(s + 2) * (1.0f / 63.0f)) * inv_sigma;
        r = __expf(-0.5f * tt * tt); nm2 = fmaf(r, g2, nm2); dn2 += r;
        tt = (x - (float)(s + 3) * (1.0f / 63.0f)) * inv_sigma;
        r = __expf(-0.5f * tt * tt); nm3 = fmaf(r, g3, nm3); dn3 += r;
    }
#pragma unroll 1
    for (; s <= s1; s++) {
        const float tt = (x - (float)s * (1.0f / 63.0f)) * inv_sigma;
        const float r = __expf(-0.5f * tt * tt);
        nm0 = fmaf(r, g_u[s * NPTS + n], nm0); dn0 += r;
    }
    const float num = (nm0 + nm1) + (nm2 + nm3);
    const float den = (dn0 + dn1) + (dn2 + dn3);
    out[n] = tanh_acc(5.0f * x) * (num / den);
}

// ---------------------------------------------------------------------------
// Inputs: x, W0, b0, W1, b1, W2, b2, W3, b3. Output fp32 [65536].
// ---------------------------------------------------------------------------
extern "C" void kernel_launch(void* const* d_in, const int* in_sizes, int n_in,
                              void* d_out, int out_size) {
    const float* X  = (const float*)d_in[0];
    const float* W0 = (const float*)d_in[1];
    const float* B0 = (const float*)d_in[2];
    const float* W1 = (const float*)d_in[3];
    const float* B1 = (const float*)d_in[4];
    const float* W2 = (const float*)d_in[5];
    const float* B2 = (const float*)d_in[6];
    const float* W3 = (const float*)d_in[7];
    const float* B3 = (const float*)d_in[8];
    float* out = (float*)d_out;

    cudaFuncSetAttribute(fbpinn_mlp, cudaFuncAttributeMaxDynamicSharedMemorySize,
                         (int)sizeof(SMem));

    const int prep_elems = 2 * NSUB * 4096;
    prep_weights<<<(prep_elems + 255) / 256, 256>>>(W1, W2);
    bin_points<<<NPTS / 256, 256>>>(X);
    dim3 grid(GRIDX, NSUB);
    fbpinn_mlp<<<grid, TPB, sizeof(SMem)>>>(X, W0, B0, B1, B2, W3, B3);
    fbpinn_reduce_kernel<<<NPTS / 128, 128>>>(X, out);
}

// round 16
// speedup vs baseline: 1.5993x; 1.1368x over previous
#include <cuda_runtime.h>
#include <cstdint>

#define NSUB  64
#define NPTS  65536
#define TPB   256         // 8 warps; each warp owns 32 of the tile's 256 points
#define TILES 4           // 256-pt tiles per CTA (finer grain -> better waves)
#define GRIDX 13          // slots per subdomain = 13*4*256 = 13312 (max 12288+10sigma)
#define STR   68          // H row stride (floats): conflict-free frag access
#define RWIN  0.0859375f  // 5.5/64 — PoU window radius (measured rel_err 3.7e-4; FINAL)
#define MAXSR 13          // max s-range per bin (analytic bound 12, +1 slack)

// Static device scratch (no allocation).
__device__ float    g_u[NSUB * NPTS];
// Fragment-packed tf32 weights: [l][s][ ((kk*4+c)*32 + lane)*4 + i ]
__device__ uint32_t gBp[2][NSUB][4096];
__device__ int      g_bin_cnt[64];
__device__ int      g_bin_idx[64][NPTS];

// ---------------------------------------------------------------------------
// Scalar helpers
// ---------------------------------------------------------------------------
__device__ __forceinline__ float tanh_hw(float x) {
    float r; asm("tanh.approx.f32 %0, %1;" : "=f"(r) : "f"(x)); return r;
}
__device__ __forceinline__ float tanh_acc(float x) {
    float e; asm("ex2.approx.f32 %0, %1;" : "=f"(e) : "f"(x * 2.8853900817779268f));
    float r; asm("rcp.approx.f32 %0, %1;" : "=f"(r) : "f"(e + 1.0f));
    return fmaf(-2.0f, r, 1.0f);
}
__device__ __forceinline__ uint32_t f2tf32(float f) {
    uint32_t r; asm("cvt.rna.tf32.f32 %0, %1;" : "=r"(r) : "f"(f)); return r;
}

// PoU bin window — single definition shared by MLP (writer) and reduce (reader).
__device__ __forceinline__ void window_of(int s, int& lo, int& hi) {
    const float c = (float)s * (1.0f / 63.0f);
    int l = (int)floorf((c - RWIN) * 64.0f);
    int h = (int)floorf((c + RWIN) * 64.0f);
    lo = l < 0 ? 0 : l;
    hi = h > 63 ? 63 : h;
}
__device__ __forceinline__ int bin_of(float x) {
    int b = (int)(x * 64.0f);
    return b < 0 ? 0 : (b > 63 ? 63 : b);
}

// mma.sync m16n8k8 tf32 (baseline PTX, tensor pipe). A operands carry raw f32
// bits: tf32 HMMA reads only the top 19 bits (truncation, err ~2^-11).
__device__ __forceinline__ void mma8(float& d0, float& d1, float& d2, float& d3,
                                     uint32_t a0, uint32_t a1, uint32_t a2, uint32_t a3,
                                     uint32_t b0, uint32_t b1) {
    asm volatile(
        "mma.sync.aligned.m16n8k8.row.col.f32.tf32.tf32.f32 "
        "{%0,%1,%2,%3}, {%4,%5,%6,%7}, {%8,%9}, {%0,%1,%2,%3};"
        : "+f"(d0), "+f"(d1), "+f"(d2), "+f"(d3)
        : "r"(a0), "r"(a1), "r"(a2), "r"(a3), "r"(b0), "r"(b1));
}

// ---------------------------------------------------------------------------
// Prep: COALESCED reads, scattered fire-and-forget stores into the
// fragment-packed layout. Also zeroes bin counters (stream-ordered first).
// ---------------------------------------------------------------------------
__global__ void prep_weights(const float* __restrict__ W1,
                             const float* __restrict__ W2) {
    const int i = blockIdx.x * 256 + threadIdx.x;          // over 2*64*4096
    if (blockIdx.x == 0 && threadIdx.x < 64) g_bin_cnt[threadIdx.x] = 0;
    if (i >= 2 * NSUB * 4096) return;
    const int l = i >> 18;                // layer
    const int r = i & 262143;             // s*4096 + n*64 + k
    const int s = r >> 12;
    const int n = (r >> 6) & 63;
    const int k = r & 63;
    // inverse fragment map: lane=(g,t), chunk c, slot ii
    const int nt = n >> 3, g = n & 7;
    const int kk = k >> 3, t = k & 3, wh = (k >> 2) & 1;
    const int j  = wh * 8 + nt;           // 0..15
    const int c  = j >> 2, ii = j & 3;
    const int lane = g * 4 + t;
    const int q  = ((kk * 4 + c) * 32 + lane) * 4 + ii;
    const float v = l ? W2[r] : W1[r];
    gBp[l][s][q] = f2tf32(v);
}
__global__ void bin_points(const float* __restrict__ X) {
    const int n = blockIdx.x * 256 + threadIdx.x;
    const int b = bin_of(X[n]);
    const int p = atomicAdd(&g_bin_cnt[b], 1);
    g_bin_idx[b][p] = n;
}

// ---------------------------------------------------------------------------
// Shared memory (~103 KB -> 2 CTAs/SM; 8 warps/CTA -> 16 warps/SM = 4/SMSP).
// Regs capped at 128 by launch_bounds (measured exactly 128 -> no spill).
// ---------------------------------------------------------------------------
struct __align__(16) SMem {
    uint32_t Bp1[4096];            // 16 KB fragment-packed W1
    uint32_t Bp2[4096];            // 16 KB fragment-packed W2
    uint32_t H[8][32 * STR];       // per-warp activations (8 warps)
    float w0[64], b0[64], b1[64], b2[64], w3[64];
    float b3;
    int cum[24];
};

__device__ __forceinline__ int slot_to_n(const int* __restrict__ cum, int nb,
                                         int lo, int slot) {
    int j = 0;
#pragma unroll 1
    while (j + 1 < nb && slot >= cum[j + 1]) j++;
    return g_bin_idx[lo + j][slot - cum[j]];
}

// ---------------------------------------------------------------------------
// Main kernel (proven R12-R15 body; finer CTA grain for wave balance).
// Fragment maps (m16n8k8, g = lane>>2, t = lane&3):
//   A: a0=(g,t) a1=(g+8,t) a2=(g,t+4) a3=(g+8,t+4)
//   B (packed): u0..u3 per kk -> bv0[nt], bv1[nt]
//   D: c0=(g,2t) c1=(g,2t+1) c2=(g+8,2t) c3=(g+8,2t+1)
// ---------------------------------------------------------------------------
__global__ __launch_bounds__(TPB, 2)
void fbpinn_mlp(const float* __restrict__ X,
                const float* __restrict__ W0g, const float* __restrict__ B0g,
                const float* __restrict__ B1g, const float* __restrict__ B2g,
                const float* __restrict__ W3g, const float* __restrict__ B3g) {
    extern __shared__ char smraw[];
    SMem* sm = (SMem*)smraw;

    const int s    = blockIdx.y;
    const int tid  = threadIdx.x;
    const int wid  = tid >> 5;
    const int lane = tid & 31;
    const int g    = lane >> 2;
    const int t    = lane & 3;
    const int wb   = wid * 32;

    int lo, hi;
    window_of(s, lo, hi);
    const int nb = hi - lo + 1;

    if (tid < nb) sm->cum[tid + 1] = g_bin_cnt[lo + tid];
    if (tid == 0) sm->cum[0] = 0;
    __syncthreads();
    if (tid == 0) {
        int a = 0;
#pragma unroll 1
        for (int j = 1; j <= nb; j++) { a += sm->cum[j]; sm->cum[j] = a; }
    }
    __syncthreads();
    const int total = sm->cum[nb];
    if (blockIdx.x * (TILES * TPB) >= total) return;

    // cooperative smem fill: B tiles (coalesced uint4) + params
    {
        const uint4* s1 = (const uint4*)&gBp[0][s][0];
        const uint4* s2 = (const uint4*)&gBp[1][s][0];
        uint4* d1 = (uint4*)sm->Bp1;
        uint4* d2 = (uint4*)sm->Bp2;
        for (int i = tid; i < 1024; i += TPB) { d1[i] = s1[i]; d2[i] = s2[i]; }
        if (tid < 64) {
            sm->w0[tid] = W0g[s * 64 + tid];
            sm->b0[tid] = B0g[s * 64 + tid];
            sm->b1[tid] = B1g[s * 64 + tid];
            sm->b2[tid] = B2g[s * 64 + tid];
            sm->w3[tid] = W3g[s * 64 + tid];
        }
        if (tid == 64) sm->b3 = B3g[s];
    }
    __syncthreads();

    const float b3v = sm->b3;
    uint32_t* Hu = sm->H[wid];
    const uint4* bp1 = (const uint4*)sm->Bp1;
    const uint4* bp2 = (const uint4*)sm->Bp2;
    float acc[8][2][4];

#pragma unroll 1
    for (int tile = 0; tile < TILES; tile++) {
        const int tb = (blockIdx.x * TILES + tile) * TPB;
        if (tb >= total) break;

        const int r0 = tb + wb + g, r1 = r0 + 8, r2 = r0 + 16, r3 = r0 + 24;
        int n0 = -1, n1 = -1, n2 = -1, n3 = -1;
        float x0 = 0.f, x1 = 0.f, x2 = 0.f, x3 = 0.f;
        if (r0 < total) { n0 = slot_to_n(sm->cum, nb, lo, r0); x0 = X[n0]; }
        if (r1 < total) { n1 = slot_to_n(sm->cum, nb, lo, r1); x1 = X[n1]; }
        if (r2 < total) { n2 = slot_to_n(sm->cum, nb, lo, r2); x2 = X[n2]; }
        if (r3 < total) { n3 = slot_to_n(sm->cum, nb, lo, r3); x3 = X[n3]; }

        // ================= Layer 1 (A built on the fly from layer 0) ========
#pragma unroll
        for (int nt = 0; nt < 8; nt++) {
            const float2 bb = *(const float2*)&sm->b1[nt * 8 + 2 * t];
#pragma unroll
            for (int mt = 0; mt < 2; mt++) {
                acc[nt][mt][0] = bb.x; acc[nt][mt][1] = bb.y;
                acc[nt][mt][2] = bb.x; acc[nt][mt][3] = bb.y;
            }
        }
#pragma unroll
        for (int kk = 0; kk < 8; kk++) {
            const int k0 = kk * 8;
            const float wc0 = sm->w0[k0 + t],     bc0 = sm->b0[k0 + t];
            const float wc1 = sm->w0[k0 + t + 4], bc1 = sm->b0[k0 + t + 4];
            uint32_t a0[4], a1[4];
            a0[0] = __float_as_uint(tanh_hw(fmaf(wc0, x0, bc0)));
            a0[1] = __float_as_uint(tanh_hw(fmaf(wc0, x1, bc0)));
            a0[2] = __float_as_uint(tanh_hw(fmaf(wc1, x0, bc1)));
            a0[3] = __float_as_uint(tanh_hw(fmaf(wc1, x1, bc1)));
            a1[0] = __float_as_uint(tanh_hw(fmaf(wc0, x2, bc0)));
            a1[1] = __float_as_uint(tanh_hw(fmaf(wc0, x3, bc0)));
            a1[2] = __float_as_uint(tanh_hw(fmaf(wc1, x2, bc1)));
            a1[3] = __float_as_uint(tanh_hw(fmaf(wc1, x3, bc1)));
            // packed B fragments: 4 x LDS.128, conflict-free
            const uint4 u0 = bp1[(kk * 4 + 0) * 32 + lane];
            const uint4 u1 = bp1[(kk * 4 + 1) * 32 + lane];
            const uint4 u2 = bp1[(kk * 4 + 2) * 32 + lane];
            const uint4 u3 = bp1[(kk * 4 + 3) * 32 + lane];
            const uint32_t bv0[8] = {u0.x, u0.y, u0.z, u0.w, u1.x, u1.y, u1.z, u1.w};
            const uint32_t bv1[8] = {u2.x, u2.y, u2.z, u2.w, u3.x, u3.y, u3.z, u3.w};
#pragma unroll
            for (int nt = 0; nt < 8; nt++) {
                mma8(acc[nt][0][0], acc[nt][0][1], acc[nt][0][2], acc[nt][0][3],
                     a0[0], a0[1], a0[2], a0[3], bv0[nt], bv1[nt]);
                mma8(acc[nt][1][0], acc[nt][1][1], acc[nt][1][2], acc[nt][1][3],
                     a1[0], a1[1], a1[2], a1[3], bv0[nt], bv1[nt]);
            }
        }

        // epilogue 1: tanh -> raw f32 bits -> per-warp H
        __syncwarp();
#pragma unroll
        for (int nt = 0; nt < 8; nt++) {
#pragma unroll
            for (int mt = 0; mt < 2; mt++) {
                uint2 lov, hiv;
                lov.x = __float_as_uint(tanh_hw(acc[nt][mt][0]));
                lov.y = __float_as_uint(tanh_hw(acc[nt][mt][1]));
                hiv.x = __float_as_uint(tanh_hw(acc[nt][mt][2]));
                hiv.y = __float_as_uint(tanh_hw(acc[nt][mt][3]));
                *(uint2*)&Hu[(mt * 16 + g) * STR + nt * 8 + 2 * t]     = lov;
                *(uint2*)&Hu[(mt * 16 + g + 8) * STR + nt * 8 + 2 * t] = hiv;
            }
        }
        __syncwarp();

        // ================= Layer 2 (A from H) ===============================
#pragma unroll
        for (int nt = 0; nt < 8; nt++) {
            const float2 bb = *(const float2*)&sm->b2[nt * 8 + 2 * t];
#pragma unroll
            for (int mt = 0; mt < 2; mt++) {
                acc[nt][mt][0] = bb.x; acc[nt][mt][1] = bb.y;
                acc[nt][mt][2] = bb.x; acc[nt][mt][3] = bb.y;
            }
        }
#pragma unroll
        for (int kk = 0; kk < 8; kk++) {
            const int k0 = kk * 8;
            uint32_t a0[4], a1[4];
            a0[0] = Hu[(g) * STR + k0 + t];
            a0[1] = Hu[(g + 8) * STR + k0 + t];
            a0[2] = Hu[(g) * STR + k0 + t + 4];
            a0[3] = Hu[(g + 8) * STR + k0 + t + 4];
            a1[0] = Hu[(g + 16) * STR + k0 + t];
            a1[1] = Hu[(g + 24) * STR + k0 + t];
            a1[2] = Hu[(g + 16) * STR + k0 + t + 4];
            a1[3] = Hu[(g + 24) * STR + k0 + t + 4];
            const uint4 u0 = bp2[(kk * 4 + 0) * 32 + lane];
            const uint4 u1 = bp2[(kk * 4 + 1) * 32 + lane];
            const uint4 u2 = bp2[(kk * 4 + 2) * 32 + lane];
            const uint4 u3 = bp2[(kk * 4 + 3) * 32 + lane];
            const uint32_t bv0[8] = {u0.x, u0.y, u0.z, u0.w, u1.x, u1.y, u1.z, u1.w};
            const uint32_t bv1[8] = {u2.x, u2.y, u2.z, u2.w, u3.x, u3.y, u3.z, u3.w};
#pragma unroll
            for (int nt = 0; nt < 8; nt++) {
                mma8(acc[nt][0][0], acc[nt][0][1], acc[nt][0][2], acc[nt][0][3],
                     a0[0], a0[1], a0[2], a0[3], bv0[nt], bv1[nt]);
                mma8(acc[nt][1][0], acc[nt][1][1], acc[nt][1][2], acc[nt][1][3],
                     a1[0], a1[1], a1[2], a1[3], bv0[nt], bv1[nt]);
            }
        }

        // ===== output layer (fp32): u[row] = b3 + sum_n w3[n]*tanh(acc) =====
        {
            float u0 = 0.f, u1 = 0.f, u2 = 0.f, u3 = 0.f;
#pragma unroll
            for (int nt = 0; nt < 8; nt++) {
                const float2 w3p = *(const float2*)&sm->w3[nt * 8 + 2 * t];
                u0 = fmaf(w3p.x, tanh_hw(acc[nt][0][0]), u0);
                u0 = fmaf(w3p.y, tanh_hw(acc[nt][0][1]), u0);
                u1 = fmaf(w3p.x, tanh_hw(acc[nt][0][2]), u1);
                u1 = fmaf(w3p.y, tanh_hw(acc[nt][0][3]), u1);
                u2 = fmaf(w3p.x, tanh_hw(acc[nt][1][0]), u2);
                u2 = fmaf(w3p.y, tanh_hw(acc[nt][1][1]), u2);
                u3 = fmaf(w3p.x, tanh_hw(acc[nt][1][2]), u3);
                u3 = fmaf(w3p.y, tanh_hw(acc[nt][1][3]), u3);
            }
#pragma unroll
            for (int d = 1; d < 4; d <<= 1) {
                u0 += __shfl_xor_sync(0xffffffffu, u0, d);
                u1 += __shfl_xor_sync(0xffffffffu, u1, d);
                u2 += __shfl_xor_sync(0xffffffffu, u2, d);
                u3 += __shfl_xor_sync(0xffffffffu, u3, d);
            }
            if (t == 0) {
                float* up = g_u + s * NPTS;
                if (n0 >= 0) up[n0] = u0 + b3v;
                if (n1 >= 0) up[n1] = u1 + b3v;
                if (n2 >= 0) up[n2] = u2 + b3v;
                if (n3 >= 0) up[n3] = u3 + b3v;
            }
        }
    }
}

// ---------------------------------------------------------------------------
// Reduce: per-bin contiguous s-range from the SAME window_of as the writer.
// Fully predicated MAXSR-wide unroll: all ~12 g_u loads issue back-to-back
// (clamped index keeps OOB lanes at a safe address; weight forced to 0, so
// ascending-order sums are bit-identical to the serial loop).
// ---------------------------------------------------------------------------
__global__ __launch_bounds__(128)
void fbpinn_reduce_kernel(const float* __restrict__ X, float* __restrict__ out) {
    __shared__ int ssmin[64], ssmax[64];
    const int tid = threadIdx.x;
    if (tid < 64) {
        int mn = 64, mx = -1;
#pragma unroll 1
        for (int s = 0; s < 64; s++) {
            int lo, hi;
            window_of(s, lo, hi);
            if (tid >= lo && tid <= hi) { if (s < mn) mn = s; if (s > mx) mx = s; }
        }
        ssmin[tid] = mn;
        ssmax[tid] = mx;
    }
    __syncthreads();

    const int n = blockIdx.x * 128 + tid;
    const float x = X[n];
    const int b = bin_of(x);
    const int s0 = ssmin[b], s1 = ssmax[b];
    const float inv_sigma = 64.0f / 1.5f;

    float gv[MAXSR];
#pragma unroll
    for (int j = 0; j < MAXSR; j++) {
        const int s = s0 + j;
        const int sc = s <= s1 ? s : s1;       // clamp -> always-safe address
        gv[j] = g_u[sc * NPTS + n];
    }
    float num = 0.f, den = 0.f;
#pragma unroll
    for (int j = 0; j < MAXSR; j++) {
        const int s = s0 + j;
        const float tt = (x - (float)s * (1.0f / 63.0f)) * inv_sigma;
        float r = __expf(-0.5f * tt * tt);
        r = (s <= s1) ? r : 0.0f;
        num = fmaf(r, gv[j], num);
        den += r;
    }
    out[n] = tanh_acc(5.0f * x) * (num / den);
}

// ---------------------------------------------------------------------------
// Inputs: x, W0, b0, W1, b1, W2, b2, W3, b3. Output fp32 [65536].
// ---------------------------------------------------------------------------
extern "C" void kernel_launch(void* const* d_in, const int* in_sizes, int n_in,
                              void* d_out, int out_size) {
    const float* X  = (const float*)d_in[0];
    const float* W0 = (const float*)d_in[1];
    const float* B0 = (const float*)d_in[2];
    const float* W1 = (const float*)d_in[3];
    const float* B1 = (const float*)d_in[4];
    const float* W2 = (const float*)d_in[5];
    const float* B2 = (const float*)d_in[6];
    const float* W3 = (const float*)d_in[7];
    const float* B3 = (const float*)d_in[8];
    float* out = (float*)d_out;

    cudaFuncSetAttribute(fbpinn_mlp, cudaFuncAttributeMaxDynamicSharedMemorySize,
                         (int)sizeof(SMem));

    const int prep_elems = 2 * NSUB * 4096;
    prep_weights<<<(prep_elems + 255) / 256, 256>>>(W1, W2);
    bin_points<<<NPTS / 256, 256>>>(X);
    dim3 grid(GRIDX, NSUB);
    fbpinn_mlp<<<grid, TPB, sizeof(SMem)>>>(X, W0, B0, B1, B2, W3, B3);
    fbpinn_reduce_kernel<<<NPTS / 128, 128>>>(X, out);
}